// round 5
// baseline (speedup 1.0000x reference)
#include <cuda_runtime.h>
#include <cuda_bf16.h>
#include <cstdint>

// ---------------- problem constants ----------------
#define SEQ   8192
#define EMB   768
#define HD    512          // per-direction hidden
#define G4    2048         // 4*HD
#define NTAG  14
#define START_IDX 12
#define STOP_IDX  13
#define NEGBIG (-1e30f)

#define REC_BLOCKS_PER_DIR 64   // 64+64 = 128 CTAs of 256 thr, all co-resident
#define CHUNK  64               // CRF chunk length
#define NCHUNK (SEQ / CHUNK)    // 128

// ---------------- device scratch (static; no allocations) ----------------
__device__ float              g_xg[2][SEQ * G4];   // gate-interleaved [t][dim][gate]
__device__ float              g_hs[2][SEQ * HD];   // hidden states (for feats)
__device__ float              g_feats[SEQ * NTAG];
__device__ unsigned long long g_hp[2][2][HD];      // [dir][parity][dim] = (tag<<32)|bits
__device__ float              g_chunkM[NCHUNK][NTAG][NTAG];

// ---------------- helpers ----------------
__device__ __forceinline__ float sigf(float x) {
    return __fdividef(1.0f, 1.0f + __expf(-x));
}
__device__ __forceinline__ float tanh_fast(float x) {
    float a = fabsf(x);
    float e = __expf(-2.0f * a);                 // in (0,1], never overflows
    float t = __fdividef(1.0f - e, 1.0f + e);
    return copysignf(t, x);
}
__device__ __forceinline__ unsigned long long ld_relaxed_u64(const unsigned long long* p) {
    unsigned long long v;
    asm volatile("ld.relaxed.gpu.global.b64 %0, [%1];" : "=l"(v) : "l"(p) : "memory");
    return v;
}
__device__ __forceinline__ void st_relaxed_u64(unsigned long long* p, unsigned long long v) {
    asm volatile("st.relaxed.gpu.global.b64 [%0], %1;" :: "l"(p), "l"(v) : "memory");
}

// =====================================================================
// 1) GEMM: xg[dir] = embeds @ w_ih^T (+ b_ih + b_hh), gate-interleaved
//    (R2 plain-FFMA version — known good)
// =====================================================================
#define BM 128
#define BN 128
#define BK 16
__global__ void __launch_bounds__(256, 2) gemm_xg(
    const float* __restrict__ emb,
    const float* __restrict__ wih_f, const float* __restrict__ bih_f, const float* __restrict__ bhh_f,
    const float* __restrict__ wih_b, const float* __restrict__ bih_b, const float* __restrict__ bhh_b)
{
    const int dir = blockIdx.z;
    const float* __restrict__ W  = dir ? wih_b : wih_f;
    const float* __restrict__ b1 = dir ? bih_b : bih_f;
    const float* __restrict__ b2 = dir ? bhh_b : bhh_f;
    float* __restrict__ out = g_xg[dir];

    __shared__ float As[BK][BM + 4];
    __shared__ float Bs[BK][BN + 4];

    const int tx = threadIdx.x;                  // 0..255
    const int m0 = blockIdx.y * BM;
    const int n0 = blockIdx.x * BN;
    const int tm = (tx >> 4) * 8;
    const int tn = (tx & 15) * 8;

    float acc[8][8] = {};

    for (int k0 = 0; k0 < EMB; k0 += BK) {
        #pragma unroll
        for (int i = 0; i < 2; i++) {
            int idx = tx + i * 256;
            int r   = idx >> 2;
            int c4  = (idx & 3) * 4;
            float4 v = *(const float4*)&emb[(m0 + r) * EMB + k0 + c4];
            As[c4 + 0][r] = v.x; As[c4 + 1][r] = v.y;
            As[c4 + 2][r] = v.z; As[c4 + 3][r] = v.w;
        }
        #pragma unroll
        for (int i = 0; i < 2; i++) {
            int idx = tx + i * 256;
            int r   = idx >> 2;
            int c4  = (idx & 3) * 4;
            float4 v = *(const float4*)&W[(n0 + r) * EMB + k0 + c4];
            Bs[c4 + 0][r] = v.x; Bs[c4 + 1][r] = v.y;
            Bs[c4 + 2][r] = v.z; Bs[c4 + 3][r] = v.w;
        }
        __syncthreads();
        #pragma unroll
        for (int kk = 0; kk < BK; kk++) {
            float a[8], b[8];
            #pragma unroll
            for (int i = 0; i < 8; i++) a[i] = As[kk][tm + i];
            #pragma unroll
            for (int j = 0; j < 8; j++) b[j] = Bs[kk][tn + j];
            #pragma unroll
            for (int i = 0; i < 8; i++)
                #pragma unroll
                for (int j = 0; j < 8; j++)
                    acc[i][j] = fmaf(a[i], b[j], acc[i][j]);
        }
        __syncthreads();
    }

    #pragma unroll
    for (int i = 0; i < 8; i++) {
        int t = m0 + tm + i;
        #pragma unroll
        for (int j = 0; j < 8; j++) {
            int r = n0 + tn + j;
            out[t * G4 + ((r & (HD - 1)) << 2) + (r >> 9)] = acc[i][j] + b1[r] + b2[r];
        }
    }
}

// =====================================================================
// 2) init: h0 tagged 0 into parity-0 buffer, sentinel into parity-1
//    (runs every launch/replay; stream order makes it visible to lstm_rec)
// =====================================================================
__global__ void init_state(const float* __restrict__ h0)
{
    int i = threadIdx.x;                         // 512 threads
    unsigned long long v0 = (unsigned long long)__float_as_uint(h0[i]);       // tag 0
    unsigned long long v1 = (unsigned long long)__float_as_uint(h0[HD + i]);
    g_hp[0][0][i] = v0;
    g_hp[1][0][i] = v1;
    g_hp[0][1][i] = 0xFFFFFFFF00000000ull;       // sentinel tag, never matches
    g_hp[1][1][i] = 0xFFFFFFFF00000000ull;
}

// =====================================================================
// 3) BiLSTM recurrence: persistent, 128 CTAs x 256 thr.
//    Data-flow barrier: (tag,value) packed in one relaxed 8B word.
// =====================================================================
__global__ void __launch_bounds__(256, 1) lstm_rec(
    const float* __restrict__ whh_f,
    const float* __restrict__ whh_b,
    const float* __restrict__ c0)
{
    const int dir = blockIdx.x >> 6;             // 64 blocks per direction
    const int blk = blockIdx.x & 63;
    const int w   = threadIdx.x >> 5;            // warp 0..7
    const int l   = threadIdx.x & 31;
    const int j   = blk * 8 + w;                 // owned h-dim

    const float* __restrict__ W  = dir ? whh_b : whh_f;
    const float* __restrict__ xg = g_xg[dir];
    float* __restrict__ hs = g_hs[dir];
    unsigned long long* hp0 = g_hp[dir][0];
    unsigned long long* hp1 = g_hp[dir][1];

    // weights register-resident; lane l covers k = l, l+32, ..., l+480
    float wr[4][16];
    #pragma unroll
    for (int g = 0; g < 4; g++) {
        const float* wrow = &W[(g * HD + j) * HD];
        #pragma unroll
        for (int kk = 0; kk < 16; kk++) wr[g][kk] = wrow[kk * 32 + l];
    }
    float c = c0[dir * HD + j];

    __shared__ float hsh[2][HD];                 // parity double buffer

    // poll slice for this warp: pairs i0 and i1
    const int i0 = w * 64 + l;
    const int i1 = i0 + 32;

    // stage initial h (tag 0, already published by init_state; just read values)
    {
        unsigned long long a = ld_relaxed_u64(&hp0[i0]);
        unsigned long long b = ld_relaxed_u64(&hp0[i1]);
        hsh[0][i0] = __uint_as_float((unsigned)a);
        hsh[0][i1] = __uint_as_float((unsigned)b);
    }
    __syncthreads();

    // prefetch xg for step 0 (warp-uniform broadcast load)
    int s0 = dir ? (SEQ - 1) : 0;
    float4 xv = *(const float4*)&xg[s0 * G4 + j * 4];

    for (int t = 0; t < SEQ; t++) {
        const int s = dir ? (SEQ - 1 - t) : t;

        // prefetch next step's xg (hides DRAM latency by a full step)
        float4 xv_next;
        if (t + 1 < SEQ) {
            int sn = dir ? (SEQ - 2 - t) : (t + 1);
            xv_next = *(const float4*)&xg[sn * G4 + j * 4];
        } else {
            xv_next = make_float4(0.f, 0.f, 0.f, 0.f);
        }

        // h chunk from smem (parity t&1)
        const float* hcur = hsh[t & 1];
        float h[16];
        #pragma unroll
        for (int kk = 0; kk < 16; kk++) h[kk] = hcur[kk * 32 + l];

        float d0 = 0.f, d1 = 0.f, d2 = 0.f, d3 = 0.f;
        #pragma unroll
        for (int kk = 0; kk < 16; kk++) {
            d0 = fmaf(wr[0][kk], h[kk], d0);
            d1 = fmaf(wr[1][kk], h[kk], d1);
            d2 = fmaf(wr[2][kk], h[kk], d2);
            d3 = fmaf(wr[3][kk], h[kk], d3);
        }
        #pragma unroll
        for (int off = 16; off > 0; off >>= 1) {
            d0 += __shfl_down_sync(0xffffffffu, d0, off);
            d1 += __shfl_down_sync(0xffffffffu, d1, off);
            d2 += __shfl_down_sync(0xffffffffu, d2, off);
            d3 += __shfl_down_sync(0xffffffffu, d3, off);
        }

        unsigned long long* hpub = ((t + 1) & 1) ? hp1 : hp0;
        if (l == 0) {
            float gi = xv.x + d0;
            float gf = xv.y + d1;
            float gg = xv.z + d2;
            float go = xv.w + d3;
            c = sigf(gf) * c + sigf(gi) * tanh_fast(gg);
            float hn = sigf(go) * tanh_fast(c);
            // publish (tag t+1, value) as one single-copy-atomic 8B word
            st_relaxed_u64(&hpub[j],
                ((unsigned long long)(unsigned)(t + 1) << 32) | (unsigned long long)__float_as_uint(hn));
            hs[s * HD + j] = hn;
        }
        xv = xv_next;

        if (t + 1 < SEQ) {
            // data-flow wait: poll this warp's 64-pair slice for tag t+1
            const unsigned want = (unsigned)(t + 1);
            unsigned long long a, b;
            bool ok;
            do {
                a = ld_relaxed_u64(&hpub[i0]);
                b = ld_relaxed_u64(&hpub[i1]);
                ok = ((unsigned)(a >> 32) == want) && ((unsigned)(b >> 32) == want);
            } while (!__all_sync(0xffffffffu, ok));
            float* hnext = hsh[(t + 1) & 1];
            hnext[i0] = __uint_as_float((unsigned)a);
            hnext[i1] = __uint_as_float((unsigned)b);
            __syncthreads();                      // single barrier per step
        }
    }
}

// =====================================================================
// 4) feats[t, j] = [hs_f | hs_b] . w_tag[j] + b_tag[j]  (R2 version)
// =====================================================================
__global__ void feats_kernel(const float* __restrict__ w_tag,
                             const float* __restrict__ b_tag)
{
    const int t = blockIdx.x;
    const int w = threadIdx.x >> 5;              // 0..13 (tag)
    const int l = threadIdx.x & 31;
    const float* __restrict__ hf = &g_hs[0][t * HD];
    const float* __restrict__ hb = &g_hs[1][t * HD];
    const float* __restrict__ wt = &w_tag[w * 1024];

    float acc = 0.f;
    #pragma unroll
    for (int k = l; k < HD; k += 32)
        acc = fmaf(hf[k], wt[k], fmaf(hb[k], wt[HD + k], acc));
    #pragma unroll
    for (int off = 16; off > 0; off >>= 1)
        acc += __shfl_down_sync(0xffffffffu, acc, off);
    if (l == 0) g_feats[t * NTAG + w] = acc + b_tag[w];
}

// =====================================================================
// 5) CRF chunk matrices (log-semiring): Ms <- M_t (o) Ms, 64 steps/chunk
// =====================================================================
__global__ void crf_chunk(const float* __restrict__ trans)
{
    __shared__ float Ms[NTAG][NTAG + 2];
    const int tid = threadIdx.x;                 // 0..195
    const int j = tid / NTAG;
    const int i = tid % NTAG;

    float trow[NTAG];
    #pragma unroll
    for (int k = 0; k < NTAG; k++) trow[k] = trans[j * NTAG + k];

    Ms[j][i] = (i == j) ? 0.f : NEGBIG;          // semiring identity
    __syncthreads();

    const int base = blockIdx.x * CHUNK;
    for (int t = base; t < base + CHUNK; t++) {
        float fj = g_feats[t * NTAG + j];
        float vals[NTAG];
        float m = NEGBIG;
        #pragma unroll
        for (int k = 0; k < NTAG; k++) {
            vals[k] = trow[k] + Ms[k][i];
            m = fmaxf(m, vals[k]);
        }
        float s = 0.f;
        #pragma unroll
        for (int k = 0; k < NTAG; k++) s += __expf(vals[k] - m);
        float nv = m + __logf(s) + fj;
        __syncthreads();
        Ms[j][i] = nv;
        __syncthreads();
    }
    g_chunkM[blockIdx.x][j][i] = Ms[j][i];
}

// =====================================================================
// 6) gold score (parallel reduce) + chunk composition + final output
// =====================================================================
__global__ void crf_final(const float* __restrict__ trans,
                          const int* __restrict__ tags,
                          float* __restrict__ out)
{
    __shared__ float red[256];
    const int tid = threadIdx.x;

    float part = 0.f;
    for (int t = tid; t < SEQ; t += 256) {
        int tag  = tags[t];
        int prev = (t == 0) ? START_IDX : tags[t - 1];
        part += g_feats[t * NTAG + tag] + trans[tag * NTAG + prev];
    }
    red[tid] = part;
    __syncthreads();
    #pragma unroll
    for (int s = 128; s > 0; s >>= 1) {
        if (tid < s) red[tid] += red[tid + s];
        __syncthreads();
    }
    const float gold = red[0] + trans[STOP_IDX * NTAG + tags[SEQ - 1]];

    if (tid < 32) {
        const int l = tid;
        float fv = (l < NTAG) ? ((l == START_IDX) ? 0.f : NEGBIG) : NEGBIG;
        for (int cix = 0; cix < NCHUNK; cix++) {
            float vals[NTAG];
            float m = NEGBIG;
            #pragma unroll
            for (int i = 0; i < NTAG; i++) {
                float fvi = __shfl_sync(0xffffffffu, fv, i);
                float v = (l < NTAG) ? (g_chunkM[cix][l][i] + fvi) : NEGBIG;
                vals[i] = v;
                m = fmaxf(m, v);
            }
            float s = 0.f;
            #pragma unroll
            for (int i = 0; i < NTAG; i++) s += __expf(vals[i] - m);
            float nv = m + __logf(s);
            fv = (l < NTAG) ? nv : NEGBIG;
        }
        float v = (l < NTAG) ? (fv + trans[STOP_IDX * NTAG + l]) : NEGBIG;
        float m = v;
        #pragma unroll
        for (int off = 16; off > 0; off >>= 1)
            m = fmaxf(m, __shfl_xor_sync(0xffffffffu, m, off));
        float e = __expf(v - m);
        #pragma unroll
        for (int off = 16; off > 0; off >>= 1)
            e += __shfl_xor_sync(0xffffffffu, e, off);
        float fwd = m + __logf(e);
        if (l == 0) out[0] = fwd - gold;
    }
}

// =====================================================================
// launch
// =====================================================================
extern "C" void kernel_launch(void* const* d_in, const int* in_sizes, int n_in,
                              void* d_out, int out_size)
{
    const float* embeds = (const float*)d_in[0];
    const int*   tags   = (const int*)  d_in[1];
    const float* w_ih_f = (const float*)d_in[2];
    const float* w_hh_f = (const float*)d_in[3];
    const float* b_ih_f = (const float*)d_in[4];
    const float* b_hh_f = (const float*)d_in[5];
    const float* w_ih_b = (const float*)d_in[6];
    const float* w_hh_b = (const float*)d_in[7];
    const float* b_ih_b = (const float*)d_in[8];
    const float* b_hh_b = (const float*)d_in[9];
    const float* w_tag  = (const float*)d_in[10];
    const float* b_tag  = (const float*)d_in[11];
    const float* trans  = (const float*)d_in[12];
    const float* h0     = (const float*)d_in[13];
    const float* c0     = (const float*)d_in[14];
    float* out = (float*)d_out;

    dim3 gemm_grid(G4 / BN, SEQ / BM, 2);        // (16, 64, 2)
    gemm_xg<<<gemm_grid, 256>>>(embeds,
                                w_ih_f, b_ih_f, b_hh_f,
                                w_ih_b, b_ih_b, b_hh_b);

    init_state<<<1, 512>>>(h0);

    lstm_rec<<<2 * REC_BLOCKS_PER_DIR, 256>>>(w_hh_f, w_hh_b, c0);

    feats_kernel<<<SEQ, NTAG * 32>>>(w_tag, b_tag);

    crf_chunk<<<NCHUNK, NTAG * NTAG>>>(trans);

    crf_final<<<1, 256>>>(trans, tags, out);
}

// round 6
// speedup vs baseline: 1.6154x; 1.6154x over previous
#include <cuda_runtime.h>
#include <cuda_bf16.h>
#include <cstdint>

// ---------------- problem constants ----------------
#define SEQ   8192
#define EMB   768
#define HD    512          // per-direction hidden
#define G4    2048         // 4*HD
#define NTAG  14
#define START_IDX 12
#define STOP_IDX  13
#define NEGBIG (-1e30f)

#define REC_BLOCKS_PER_DIR 64   // 64+64 = 128 CTAs of 256 thr, all co-resident
#define CHUNK  64               // CRF chunk length
#define NCHUNK (SEQ / CHUNK)    // 128

// ---------------- device scratch (static; no allocations) ----------------
__device__ float    g_xg[2][SEQ * G4];          // gate-interleaved [t][dim][gate]
__device__ float    g_hs[2][SEQ * HD];          // hidden states (for feats)
__device__ float    g_feats[SEQ * NTAG];
__device__ __align__(16) float g_hbuf[2][2][HD]; // [dir][parity][dim]
__device__ unsigned g_bar[2][32];               // per-direction counter (128B apart)
__device__ float    g_chunkM[NCHUNK][NTAG][NTAG];

// ---------------- helpers ----------------
__device__ __forceinline__ float sigf(float x) {
    return __fdividef(1.0f, 1.0f + __expf(-x));
}
__device__ __forceinline__ float tanh_fast(float x) {
    float a = fabsf(x);
    float e = __expf(-2.0f * a);                 // in (0,1], never overflows
    float t = __fdividef(1.0f - e, 1.0f + e);
    return copysignf(t, x);
}

// =====================================================================
// 1) GEMM: xg[dir] = embeds @ w_ih^T (+ b_ih + b_hh), gate-interleaved
//    (R2 plain-FFMA version — measured good)
// =====================================================================
#define BM 128
#define BN 128
#define BK 16
__global__ void __launch_bounds__(256, 2) gemm_xg(
    const float* __restrict__ emb,
    const float* __restrict__ wih_f, const float* __restrict__ bih_f, const float* __restrict__ bhh_f,
    const float* __restrict__ wih_b, const float* __restrict__ bih_b, const float* __restrict__ bhh_b)
{
    const int dir = blockIdx.z;
    const float* __restrict__ W  = dir ? wih_b : wih_f;
    const float* __restrict__ b1 = dir ? bih_b : bih_f;
    const float* __restrict__ b2 = dir ? bhh_b : bhh_f;
    float* __restrict__ out = g_xg[dir];

    __shared__ float As[BK][BM + 4];
    __shared__ float Bs[BK][BN + 4];

    const int tx = threadIdx.x;                  // 0..255
    const int m0 = blockIdx.y * BM;
    const int n0 = blockIdx.x * BN;
    const int tm = (tx >> 4) * 8;
    const int tn = (tx & 15) * 8;

    float acc[8][8] = {};

    for (int k0 = 0; k0 < EMB; k0 += BK) {
        #pragma unroll
        for (int i = 0; i < 2; i++) {
            int idx = tx + i * 256;
            int r   = idx >> 2;
            int c4  = (idx & 3) * 4;
            float4 v = *(const float4*)&emb[(m0 + r) * EMB + k0 + c4];
            As[c4 + 0][r] = v.x; As[c4 + 1][r] = v.y;
            As[c4 + 2][r] = v.z; As[c4 + 3][r] = v.w;
        }
        #pragma unroll
        for (int i = 0; i < 2; i++) {
            int idx = tx + i * 256;
            int r   = idx >> 2;
            int c4  = (idx & 3) * 4;
            float4 v = *(const float4*)&W[(n0 + r) * EMB + k0 + c4];
            Bs[c4 + 0][r] = v.x; Bs[c4 + 1][r] = v.y;
            Bs[c4 + 2][r] = v.z; Bs[c4 + 3][r] = v.w;
        }
        __syncthreads();
        #pragma unroll
        for (int kk = 0; kk < BK; kk++) {
            float a[8], b[8];
            #pragma unroll
            for (int i = 0; i < 8; i++) a[i] = As[kk][tm + i];
            #pragma unroll
            for (int j = 0; j < 8; j++) b[j] = Bs[kk][tn + j];
            #pragma unroll
            for (int i = 0; i < 8; i++)
                #pragma unroll
                for (int j = 0; j < 8; j++)
                    acc[i][j] = fmaf(a[i], b[j], acc[i][j]);
        }
        __syncthreads();
    }

    #pragma unroll
    for (int i = 0; i < 8; i++) {
        int t = m0 + tm + i;
        #pragma unroll
        for (int j = 0; j < 8; j++) {
            int r = n0 + tn + j;
            out[t * G4 + ((r & (HD - 1)) << 2) + (r >> 9)] = acc[i][j] + b1[r] + b2[r];
        }
    }
}

// =====================================================================
// 2) init: h0 into parity-0 buffers, reset counters (every launch/replay)
// =====================================================================
__global__ void init_state(const float* __restrict__ h0)
{
    int i = threadIdx.x;                         // 512 threads
    g_hbuf[0][0][i] = h0[i];
    g_hbuf[1][0][i] = h0[HD + i];
    if (i < 2) g_bar[i][0] = 0u;
}

// =====================================================================
// 3) BiLSTM recurrence: persistent, 128 CTAs x 256 thr.
//    Single counter/dir; red.release arrive; poller-warp detect + stage.
// =====================================================================
__global__ void __launch_bounds__(256, 1) lstm_rec(
    const float* __restrict__ whh_f,
    const float* __restrict__ whh_b,
    const float* __restrict__ c0)
{
    const int dir = blockIdx.x >> 6;             // 64 blocks per direction
    const int blk = blockIdx.x & 63;
    const int w   = threadIdx.x >> 5;            // warp 0..7
    const int l   = threadIdx.x & 31;
    const int j   = blk * 8 + w;                 // owned h-dim

    const float* __restrict__ W  = dir ? whh_b : whh_f;
    const float* __restrict__ xg = g_xg[dir];
    float* __restrict__ hs = g_hs[dir];
    float* hb0 = g_hbuf[dir][0];
    float* hb1 = g_hbuf[dir][1];
    unsigned* bar = &g_bar[dir][0];

    // weights register-resident; lane l covers k = l, l+32, ..., l+480
    float wr[4][16];
    #pragma unroll
    for (int g = 0; g < 4; g++) {
        const float* wrow = &W[(g * HD + j) * HD];
        #pragma unroll
        for (int kk = 0; kk < 16; kk++) wr[g][kk] = wrow[kk * 32 + l];
    }
    float c = c0[dir * HD + j];                  // replicated across lanes

    __shared__ __align__(16) float hsh[2][HD];   // parity double buffer

    // stage initial h (2 floats / thread)
    hsh[0][threadIdx.x]       = __ldcg(&hb0[threadIdx.x]);
    hsh[0][threadIdx.x + 256] = __ldcg(&hb0[threadIdx.x + 256]);
    __syncthreads();

    // prefetch xg for step 0 (warp-uniform broadcast load)
    int s0 = dir ? (SEQ - 1) : 0;
    float4 xv = *(const float4*)&xg[s0 * G4 + j * 4];

    for (int t = 0; t < SEQ; t++) {
        const int s = dir ? (SEQ - 1 - t) : t;

        // prefetch next step's xg (hides DRAM latency by a full step)
        float4 xv_next;
        if (t + 1 < SEQ) {
            int sn = dir ? (SEQ - 2 - t) : (t + 1);
            xv_next = *(const float4*)&xg[sn * G4 + j * 4];
        } else {
            xv_next = make_float4(0.f, 0.f, 0.f, 0.f);
        }

        // h from smem (parity t&1); conflict-free: bank = l for all kk
        const float* hcur = hsh[t & 1];
        float h[16];
        #pragma unroll
        for (int kk = 0; kk < 16; kk++) h[kk] = hcur[kk * 32 + l];

        float d0 = 0.f, d1 = 0.f, d2 = 0.f, d3 = 0.f;
        #pragma unroll
        for (int kk = 0; kk < 16; kk++) {
            d0 = fmaf(wr[0][kk], h[kk], d0);
            d1 = fmaf(wr[1][kk], h[kk], d1);
            d2 = fmaf(wr[2][kk], h[kk], d2);
            d3 = fmaf(wr[3][kk], h[kk], d3);
        }
        // butterfly reduce -> ALL lanes hold the 4 full sums
        #pragma unroll
        for (int off = 16; off > 0; off >>= 1) {
            d0 += __shfl_xor_sync(0xffffffffu, d0, off);
            d1 += __shfl_xor_sync(0xffffffffu, d1, off);
            d2 += __shfl_xor_sync(0xffffffffu, d2, off);
            d3 += __shfl_xor_sync(0xffffffffu, d3, off);
        }

        // gate nonlinearities on lanes 0..3 in parallel
        float xval = (l == 0) ? xv.x : (l == 1) ? xv.y : (l == 2) ? xv.z : xv.w;
        float dsel = (l == 0) ? d0   : (l == 1) ? d1   : (l == 2) ? d2   : d3;
        float pre  = xval + dsel;
        float act  = (l == 2) ? tanh_fast(pre) : sigf(pre);   // i,f,o: sigmoid; g: tanh

        float si = __shfl_sync(0xffffffffu, act, 0);
        float sf = __shfl_sync(0xffffffffu, act, 1);
        float tg = __shfl_sync(0xffffffffu, act, 2);
        float so = __shfl_sync(0xffffffffu, act, 3);
        c = sf * c + si * tg;                    // replicated, deterministic
        float hn = so * tanh_fast(c);

        float* hdst = ((t + 1) & 1) ? hb1 : hb0;
        if (l == 0) {
            __stcg(&hdst[j], hn);                // publish to L2
            hs[s * HD + j] = hn;                 // history for feats
        }
        xv = xv_next;

        __syncthreads();                         // all 8 h stores issued

        if (t + 1 < SEQ) {
            if (w == 0) {
                // arrive (release orders this CTA's prior stores; syncthreads
                // extended them to all threads — canonical coop-groups pattern)
                if (l == 0)
                    asm volatile("red.release.gpu.global.add.u32 [%0], %1;"
                                 :: "l"(bar), "r"(1u) : "memory");
                // all 32 lanes spin on the SAME word (1 broadcast request/round);
                // each lane's own acquire orders its staging loads below
                const unsigned target = (unsigned)REC_BLOCKS_PER_DIR * (unsigned)(t + 1);
                unsigned v;
                do {
                    asm volatile("ld.acquire.gpu.global.u32 %0, [%1];"
                                 : "=r"(v) : "l"(bar) : "memory");
                } while (v < target);
                // stage all 512 h floats: lane l -> h[l*16 .. l*16+15]
                const float4* hsrc = (const float4*)(((t + 1) & 1) ? hb1 : hb0);
                float4* hdst4 = (float4*)hsh[(t + 1) & 1];
                float4 a = __ldcg(&hsrc[l * 4 + 0]);
                float4 b = __ldcg(&hsrc[l * 4 + 1]);
                float4 e = __ldcg(&hsrc[l * 4 + 2]);
                float4 f = __ldcg(&hsrc[l * 4 + 3]);
                hdst4[l * 4 + 0] = a;
                hdst4[l * 4 + 1] = b;
                hdst4[l * 4 + 2] = e;
                hdst4[l * 4 + 3] = f;
            }
            __syncthreads();                     // staged h visible to all
        }
    }
}

// =====================================================================
// 4) feats[t, j] = [hs_f | hs_b] . w_tag[j] + b_tag[j]  (R2 version)
// =====================================================================
__global__ void feats_kernel(const float* __restrict__ w_tag,
                             const float* __restrict__ b_tag)
{
    const int t = blockIdx.x;
    const int w = threadIdx.x >> 5;              // 0..13 (tag)
    const int l = threadIdx.x & 31;
    const float* __restrict__ hf = &g_hs[0][t * HD];
    const float* __restrict__ hb = &g_hs[1][t * HD];
    const float* __restrict__ wt = &w_tag[w * 1024];

    float acc = 0.f;
    #pragma unroll
    for (int k = l; k < HD; k += 32)
        acc = fmaf(hf[k], wt[k], fmaf(hb[k], wt[HD + k], acc));
    #pragma unroll
    for (int off = 16; off > 0; off >>= 1)
        acc += __shfl_down_sync(0xffffffffu, acc, off);
    if (l == 0) g_feats[t * NTAG + w] = acc + b_tag[w];
}

// =====================================================================
// 5) CRF chunk matrices (log-semiring): Ms <- M_t (o) Ms, 64 steps/chunk
// =====================================================================
__global__ void crf_chunk(const float* __restrict__ trans)
{
    __shared__ float Ms[NTAG][NTAG + 2];
    const int tid = threadIdx.x;                 // 0..195
    const int j = tid / NTAG;
    const int i = tid % NTAG;

    float trow[NTAG];
    #pragma unroll
    for (int k = 0; k < NTAG; k++) trow[k] = trans[j * NTAG + k];

    Ms[j][i] = (i == j) ? 0.f : NEGBIG;          // semiring identity
    __syncthreads();

    const int base = blockIdx.x * CHUNK;
    for (int t = base; t < base + CHUNK; t++) {
        float fj = g_feats[t * NTAG + j];
        float vals[NTAG];
        float m = NEGBIG;
        #pragma unroll
        for (int k = 0; k < NTAG; k++) {
            vals[k] = trow[k] + Ms[k][i];
            m = fmaxf(m, vals[k]);
        }
        float s = 0.f;
        #pragma unroll
        for (int k = 0; k < NTAG; k++) s += __expf(vals[k] - m);
        float nv = m + __logf(s) + fj;
        __syncthreads();
        Ms[j][i] = nv;
        __syncthreads();
    }
    g_chunkM[blockIdx.x][j][i] = Ms[j][i];
}

// =====================================================================
// 6) gold score (parallel reduce) + chunk composition + final output
// =====================================================================
__global__ void crf_final(const float* __restrict__ trans,
                          const int* __restrict__ tags,
                          float* __restrict__ out)
{
    __shared__ float red[256];
    const int tid = threadIdx.x;

    float part = 0.f;
    for (int t = tid; t < SEQ; t += 256) {
        int tag  = tags[t];
        int prev = (t == 0) ? START_IDX : tags[t - 1];
        part += g_feats[t * NTAG + tag] + trans[tag * NTAG + prev];
    }
    red[tid] = part;
    __syncthreads();
    #pragma unroll
    for (int s = 128; s > 0; s >>= 1) {
        if (tid < s) red[tid] += red[tid + s];
        __syncthreads();
    }
    const float gold = red[0] + trans[STOP_IDX * NTAG + tags[SEQ - 1]];

    if (tid < 32) {
        const int l = tid;
        float fv = (l < NTAG) ? ((l == START_IDX) ? 0.f : NEGBIG) : NEGBIG;
        for (int cix = 0; cix < NCHUNK; cix++) {
            float vals[NTAG];
            float m = NEGBIG;
            #pragma unroll
            for (int i = 0; i < NTAG; i++) {
                float fvi = __shfl_sync(0xffffffffu, fv, i);
                float v = (l < NTAG) ? (g_chunkM[cix][l][i] + fvi) : NEGBIG;
                vals[i] = v;
                m = fmaxf(m, v);
            }
            float s = 0.f;
            #pragma unroll
            for (int i = 0; i < NTAG; i++) s += __expf(vals[i] - m);
            float nv = m + __logf(s);
            fv = (l < NTAG) ? nv : NEGBIG;
        }
        float v = (l < NTAG) ? (fv + trans[STOP_IDX * NTAG + l]) : NEGBIG;
        float m = v;
        #pragma unroll
        for (int off = 16; off > 0; off >>= 1)
            m = fmaxf(m, __shfl_xor_sync(0xffffffffu, m, off));
        float e = __expf(v - m);
        #pragma unroll
        for (int off = 16; off > 0; off >>= 1)
            e += __shfl_xor_sync(0xffffffffu, e, off);
        float fwd = m + __logf(e);
        if (l == 0) out[0] = fwd - gold;
    }
}

// =====================================================================
// launch
// =====================================================================
extern "C" void kernel_launch(void* const* d_in, const int* in_sizes, int n_in,
                              void* d_out, int out_size)
{
    const float* embeds = (const float*)d_in[0];
    const int*   tags   = (const int*)  d_in[1];
    const float* w_ih_f = (const float*)d_in[2];
    const float* w_hh_f = (const float*)d_in[3];
    const float* b_ih_f = (const float*)d_in[4];
    const float* b_hh_f = (const float*)d_in[5];
    const float* w_ih_b = (const float*)d_in[6];
    const float* w_hh_b = (const float*)d_in[7];
    const float* b_ih_b = (const float*)d_in[8];
    const float* b_hh_b = (const float*)d_in[9];
    const float* w_tag  = (const float*)d_in[10];
    const float* b_tag  = (const float*)d_in[11];
    const float* trans  = (const float*)d_in[12];
    const float* h0     = (const float*)d_in[13];
    const float* c0     = (const float*)d_in[14];
    float* out = (float*)d_out;

    dim3 gemm_grid(G4 / BN, SEQ / BM, 2);        // (16, 64, 2)
    gemm_xg<<<gemm_grid, 256>>>(embeds,
                                w_ih_f, b_ih_f, b_hh_f,
                                w_ih_b, b_ih_b, b_hh_b);

    init_state<<<1, 512>>>(h0);

    lstm_rec<<<2 * REC_BLOCKS_PER_DIR, 256>>>(w_hh_f, w_hh_b, c0);

    feats_kernel<<<SEQ, NTAG * 32>>>(w_tag, b_tag);

    crf_chunk<<<NCHUNK, NTAG * NTAG>>>(trans);

    crf_final<<<1, 256>>>(trans, tags, out);
}

// round 7
// speedup vs baseline: 1.6173x; 1.0012x over previous
#include <cuda_runtime.h>
#include <cuda_bf16.h>
#include <cstdint>

// ---------------- problem constants ----------------
#define SEQ   8192
#define EMB   768
#define HD    512          // per-direction hidden
#define G4    2048         // 4*HD
#define NTAG  14
#define START_IDX 12
#define STOP_IDX  13
#define NEGBIG (-1e30f)

#define REC_BLOCKS_PER_DIR 64   // 64+64 = 128 CTAs of 256 thr, all co-resident
#define CHUNK  64               // CRF chunk length
#define NCHUNK (SEQ / CHUNK)    // 128

// ---------------- device scratch (static; no allocations) ----------------
__device__ float    g_xg[2][SEQ * G4];          // gate-interleaved [t][dim][gate]
__device__ float    g_hs[2][SEQ * HD];          // hidden states (for feats)
__device__ float    g_feats[SEQ * NTAG];
__device__ float    g_hbuf[2][2][HD];           // [dir][buf][dim]
__device__ unsigned g_bar[2][32];               // per-direction counter (128B apart)
__device__ float    g_chunkM[NCHUNK][NTAG][NTAG];

// ---------------- helpers ----------------
__device__ __forceinline__ float sigf(float x) {
    return __fdividef(1.0f, 1.0f + __expf(-x));
}
__device__ __forceinline__ float tanh_fast(float x) {
    float a = fabsf(x);
    float e = __expf(-2.0f * a);                 // in (0,1], never overflows
    float t = __fdividef(1.0f - e, 1.0f + e);
    return copysignf(t, x);
}

// =====================================================================
// 1) GEMM: xg[dir] = embeds @ w_ih^T (+ b_ih + b_hh), gate-interleaved
//    R2 tiling + register double-buffering of the global loads
// =====================================================================
#define BM 128
#define BN 128
#define BK 16
__global__ void __launch_bounds__(256, 2) gemm_xg(
    const float* __restrict__ emb,
    const float* __restrict__ wih_f, const float* __restrict__ bih_f, const float* __restrict__ bhh_f,
    const float* __restrict__ wih_b, const float* __restrict__ bih_b, const float* __restrict__ bhh_b)
{
    const int dir = blockIdx.z;
    const float* __restrict__ W  = dir ? wih_b : wih_f;
    const float* __restrict__ b1 = dir ? bih_b : bih_f;
    const float* __restrict__ b2 = dir ? bhh_b : bhh_f;
    float* __restrict__ out = g_xg[dir];

    __shared__ float As[BK][BM + 4];
    __shared__ float Bs[BK][BN + 4];

    const int tx = threadIdx.x;                  // 0..255
    const int m0 = blockIdx.y * BM;
    const int n0 = blockIdx.x * BN;
    const int tm = (tx >> 4) * 8;
    const int tn = (tx & 15) * 8;

    // per-thread load coordinates (two float4 slots per tile per matrix)
    const int r0  = (tx) >> 2,         c40 = (tx & 3) * 4;
    const int r1  = (tx + 256) >> 2,   c41 = ((tx + 256) & 3) * 4;

    float acc[8][8] = {};

    // prefetch first tiles into registers
    float4 pa0 = *(const float4*)&emb[(m0 + r0) * EMB + c40];
    float4 pa1 = *(const float4*)&emb[(m0 + r1) * EMB + c41];
    float4 pb0 = *(const float4*)&W  [(n0 + r0) * EMB + c40];
    float4 pb1 = *(const float4*)&W  [(n0 + r1) * EMB + c41];

    for (int k0 = 0; k0 < EMB; k0 += BK) {
        // commit prefetched registers to smem
        As[c40 + 0][r0] = pa0.x; As[c40 + 1][r0] = pa0.y;
        As[c40 + 2][r0] = pa0.z; As[c40 + 3][r0] = pa0.w;
        As[c41 + 0][r1] = pa1.x; As[c41 + 1][r1] = pa1.y;
        As[c41 + 2][r1] = pa1.z; As[c41 + 3][r1] = pa1.w;
        Bs[c40 + 0][r0] = pb0.x; Bs[c40 + 1][r0] = pb0.y;
        Bs[c40 + 2][r0] = pb0.z; Bs[c40 + 3][r0] = pb0.w;
        Bs[c41 + 0][r1] = pb1.x; Bs[c41 + 1][r1] = pb1.y;
        Bs[c41 + 2][r1] = pb1.z; Bs[c41 + 3][r1] = pb1.w;
        __syncthreads();

        // issue next tile's LDGs early — latency hidden under the FFMA block
        if (k0 + BK < EMB) {
            const int kn = k0 + BK;
            pa0 = *(const float4*)&emb[(m0 + r0) * EMB + kn + c40];
            pa1 = *(const float4*)&emb[(m0 + r1) * EMB + kn + c41];
            pb0 = *(const float4*)&W  [(n0 + r0) * EMB + kn + c40];
            pb1 = *(const float4*)&W  [(n0 + r1) * EMB + kn + c41];
        }

        #pragma unroll
        for (int kk = 0; kk < BK; kk++) {
            float a[8], b[8];
            #pragma unroll
            for (int i = 0; i < 8; i++) a[i] = As[kk][tm + i];
            #pragma unroll
            for (int j = 0; j < 8; j++) b[j] = Bs[kk][tn + j];
            #pragma unroll
            for (int i = 0; i < 8; i++)
                #pragma unroll
                for (int j = 0; j < 8; j++)
                    acc[i][j] = fmaf(a[i], b[j], acc[i][j]);
        }
        __syncthreads();
    }

    #pragma unroll
    for (int i = 0; i < 8; i++) {
        int t = m0 + tm + i;
        #pragma unroll
        for (int j = 0; j < 8; j++) {
            int r = n0 + tn + j;
            out[t * G4 + ((r & (HD - 1)) << 2) + (r >> 9)] = acc[i][j] + b1[r] + b2[r];
        }
    }
}

// =====================================================================
// 2) init: h0 into buffers, reset counters (runs every launch/replay)
// =====================================================================
__global__ void init_state(const float* __restrict__ h0)
{
    int i = threadIdx.x;                         // 512 threads
    g_hbuf[0][0][i] = h0[i];
    g_hbuf[1][0][i] = h0[HD + i];
    if (i < 2) g_bar[i][0] = 0u;
}

// =====================================================================
// 3) BiLSTM recurrence: exact R2 structure; only the arrive/spin changed
//    (red.release instead of threadfence+atomicAdd; acquire spin, 2 in flight)
// =====================================================================
__global__ void __launch_bounds__(256, 1) lstm_rec(
    const float* __restrict__ whh_f,
    const float* __restrict__ whh_b,
    const float* __restrict__ c0)
{
    const int dir = blockIdx.x >> 6;             // 64 blocks per direction
    const int blk = blockIdx.x & 63;
    const int w   = threadIdx.x >> 5;            // warp 0..7
    const int l   = threadIdx.x & 31;
    const int j   = blk * 8 + w;                 // owned h-dim

    const float* __restrict__ W  = dir ? whh_b : whh_f;
    const float* __restrict__ xg = g_xg[dir];
    float* __restrict__ hs = g_hs[dir];
    float* hb0 = g_hbuf[dir][0];
    float* hb1 = g_hbuf[dir][1];
    unsigned* bar = &g_bar[dir][0];

    // weights register-resident; lane l covers k = l, l+32, ..., l+480
    float wr[4][16];
    #pragma unroll
    for (int g = 0; g < 4; g++) {
        const float* wrow = &W[(g * HD + j) * HD];
        #pragma unroll
        for (int kk = 0; kk < 16; kk++) wr[g][kk] = wrow[kk * 32 + l];
    }
    float c = c0[dir * HD + j];

    __shared__ float hsh[HD];

    // stage initial h (2 floats / thread, as in R2)
    {
        float2 v = __ldcg((const float2*)&hb0[threadIdx.x * 2]);
        hsh[threadIdx.x * 2 + 0] = v.x;
        hsh[threadIdx.x * 2 + 1] = v.y;
    }
    __syncthreads();

    // prefetch xg for step 0 (warp-uniform broadcast load)
    int s0 = dir ? (SEQ - 1) : 0;
    float4 xv = *(const float4*)&xg[s0 * G4 + j * 4];

    for (int t = 0; t < SEQ; t++) {
        const int s = dir ? (SEQ - 1 - t) : t;

        // prefetch next step's xg (hides DRAM latency by a full step)
        float4 xv_next;
        if (t + 1 < SEQ) {
            int sn = dir ? (SEQ - 2 - t) : (t + 1);
            xv_next = *(const float4*)&xg[sn * G4 + j * 4];
        } else {
            xv_next = make_float4(0.f, 0.f, 0.f, 0.f);
        }

        // h chunk from smem
        float h[16];
        #pragma unroll
        for (int kk = 0; kk < 16; kk++) h[kk] = hsh[kk * 32 + l];

        float d0 = 0.f, d1 = 0.f, d2 = 0.f, d3 = 0.f;
        #pragma unroll
        for (int kk = 0; kk < 16; kk++) {
            d0 = fmaf(wr[0][kk], h[kk], d0);
            d1 = fmaf(wr[1][kk], h[kk], d1);
            d2 = fmaf(wr[2][kk], h[kk], d2);
            d3 = fmaf(wr[3][kk], h[kk], d3);
        }
        #pragma unroll
        for (int off = 16; off > 0; off >>= 1) {
            d0 += __shfl_down_sync(0xffffffffu, d0, off);
            d1 += __shfl_down_sync(0xffffffffu, d1, off);
            d2 += __shfl_down_sync(0xffffffffu, d2, off);
            d3 += __shfl_down_sync(0xffffffffu, d3, off);
        }

        float* hdst = (t & 1) ? hb0 : hb1;
        if (l == 0) {
            float gi = xv.x + d0;
            float gf = xv.y + d1;
            float gg = xv.z + d2;
            float go = xv.w + d3;
            c = sigf(gf) * c + sigf(gi) * tanh_fast(gg);
            float hn = sigf(go) * tanh_fast(c);
            __stcg(&hdst[j], hn);                // L2-visible for other SMs
            hs[s * HD + j] = hn;
        }
        xv = xv_next;

        __syncthreads();                          // block's h stores done
        if (threadIdx.x == 0) {
            // release-arrive covers all threads' prior stores (via syncthreads)
            asm volatile("red.release.gpu.global.add.u32 [%0], %1;"
                         :: "l"(bar), "r"(1u) : "memory");
            const unsigned target = (unsigned)REC_BLOCKS_PER_DIR * (unsigned)(t + 1);
            unsigned v1, v2;
            do {                                  // 2 independent loads in flight
                asm volatile("ld.acquire.gpu.global.u32 %0, [%2];\n\t"
                             "ld.acquire.gpu.global.u32 %1, [%2];"
                             : "=r"(v1), "=r"(v2) : "l"(bar) : "memory");
            } while (v1 < target && v2 < target);
        }
        __syncthreads();

        // stage the just-produced h for the next step (as in R2)
        if (t + 1 < SEQ) {
            const float* hsrc = (t & 1) ? hb0 : hb1;
            float2 v = __ldcg((const float2*)&hsrc[threadIdx.x * 2]);
            hsh[threadIdx.x * 2 + 0] = v.x;
            hsh[threadIdx.x * 2 + 1] = v.y;
            __syncthreads();
        }
    }
}

// =====================================================================
// 4) feats[t, j] = [hs_f | hs_b] . w_tag[j] + b_tag[j]  (R2 version)
// =====================================================================
__global__ void feats_kernel(const float* __restrict__ w_tag,
                             const float* __restrict__ b_tag)
{
    const int t = blockIdx.x;
    const int w = threadIdx.x >> 5;              // 0..13 (tag)
    const int l = threadIdx.x & 31;
    const float* __restrict__ hf = &g_hs[0][t * HD];
    const float* __restrict__ hb = &g_hs[1][t * HD];
    const float* __restrict__ wt = &w_tag[w * 1024];

    float acc = 0.f;
    #pragma unroll
    for (int k = l; k < HD; k += 32)
        acc = fmaf(hf[k], wt[k], fmaf(hb[k], wt[HD + k], acc));
    #pragma unroll
    for (int off = 16; off > 0; off >>= 1)
        acc += __shfl_down_sync(0xffffffffu, acc, off);
    if (l == 0) g_feats[t * NTAG + w] = acc + b_tag[w];
}

// =====================================================================
// 5) CRF chunk matrices (log-semiring): Ms <- M_t (o) Ms, 64 steps/chunk
// =====================================================================
__global__ void crf_chunk(const float* __restrict__ trans)
{
    __shared__ float Ms[NTAG][NTAG + 2];
    const int tid = threadIdx.x;                 // 0..195
    const int j = tid / NTAG;
    const int i = tid % NTAG;

    float trow[NTAG];
    #pragma unroll
    for (int k = 0; k < NTAG; k++) trow[k] = trans[j * NTAG + k];

    Ms[j][i] = (i == j) ? 0.f : NEGBIG;          // semiring identity
    __syncthreads();

    const int base = blockIdx.x * CHUNK;
    for (int t = base; t < base + CHUNK; t++) {
        float fj = g_feats[t * NTAG + j];
        float vals[NTAG];
        float m = NEGBIG;
        #pragma unroll
        for (int k = 0; k < NTAG; k++) {
            vals[k] = trow[k] + Ms[k][i];
            m = fmaxf(m, vals[k]);
        }
        float s = 0.f;
        #pragma unroll
        for (int k = 0; k < NTAG; k++) s += __expf(vals[k] - m);
        float nv = m + __logf(s) + fj;
        __syncthreads();
        Ms[j][i] = nv;
        __syncthreads();
    }
    g_chunkM[blockIdx.x][j][i] = Ms[j][i];
}

// =====================================================================
// 6) gold score (parallel reduce) + chunk composition + final output
// =====================================================================
__global__ void crf_final(const float* __restrict__ trans,
                          const int* __restrict__ tags,
                          float* __restrict__ out)
{
    __shared__ float red[256];
    const int tid = threadIdx.x;

    float part = 0.f;
    for (int t = tid; t < SEQ; t += 256) {
        int tag  = tags[t];
        int prev = (t == 0) ? START_IDX : tags[t - 1];
        part += g_feats[t * NTAG + tag] + trans[tag * NTAG + prev];
    }
    red[tid] = part;
    __syncthreads();
    #pragma unroll
    for (int s = 128; s > 0; s >>= 1) {
        if (tid < s) red[tid] += red[tid + s];
        __syncthreads();
    }
    const float gold = red[0] + trans[STOP_IDX * NTAG + tags[SEQ - 1]];

    if (tid < 32) {
        const int l = tid;
        float fv = (l < NTAG) ? ((l == START_IDX) ? 0.f : NEGBIG) : NEGBIG;
        for (int cix = 0; cix < NCHUNK; cix++) {
            float vals[NTAG];
            float m = NEGBIG;
            #pragma unroll
            for (int i = 0; i < NTAG; i++) {
                float fvi = __shfl_sync(0xffffffffu, fv, i);
                float v = (l < NTAG) ? (g_chunkM[cix][l][i] + fvi) : NEGBIG;
                vals[i] = v;
                m = fmaxf(m, v);
            }
            float s = 0.f;
            #pragma unroll
            for (int i = 0; i < NTAG; i++) s += __expf(vals[i] - m);
            float nv = m + __logf(s);
            fv = (l < NTAG) ? nv : NEGBIG;
        }
        float v = (l < NTAG) ? (fv + trans[STOP_IDX * NTAG + l]) : NEGBIG;
        float m = v;
        #pragma unroll
        for (int off = 16; off > 0; off >>= 1)
            m = fmaxf(m, __shfl_xor_sync(0xffffffffu, m, off));
        float e = __expf(v - m);
        #pragma unroll
        for (int off = 16; off > 0; off >>= 1)
            e += __shfl_xor_sync(0xffffffffu, e, off);
        float fwd = m + __logf(e);
        if (l == 0) out[0] = fwd - gold;
    }
}

// =====================================================================
// launch
// =====================================================================
extern "C" void kernel_launch(void* const* d_in, const int* in_sizes, int n_in,
                              void* d_out, int out_size)
{
    const float* embeds = (const float*)d_in[0];
    const int*   tags   = (const int*)  d_in[1];
    const float* w_ih_f = (const float*)d_in[2];
    const float* w_hh_f = (const float*)d_in[3];
    const float* b_ih_f = (const float*)d_in[4];
    const float* b_hh_f = (const float*)d_in[5];
    const float* w_ih_b = (const float*)d_in[6];
    const float* w_hh_b = (const float*)d_in[7];
    const float* b_ih_b = (const float*)d_in[8];
    const float* b_hh_b = (const float*)d_in[9];
    const float* w_tag  = (const float*)d_in[10];
    const float* b_tag  = (const float*)d_in[11];
    const float* trans  = (const float*)d_in[12];
    const float* h0     = (const float*)d_in[13];
    const float* c0     = (const float*)d_in[14];
    float* out = (float*)d_out;

    dim3 gemm_grid(G4 / BN, SEQ / BM, 2);        // (16, 64, 2)
    gemm_xg<<<gemm_grid, 256>>>(embeds,
                                w_ih_f, b_ih_f, b_hh_f,
                                w_ih_b, b_ih_b, b_hh_b);

    init_state<<<1, 512>>>(h0);

    lstm_rec<<<2 * REC_BLOCKS_PER_DIR, 256>>>(w_hh_f, w_hh_b, c0);

    feats_kernel<<<SEQ, NTAG * 32>>>(w_tag, b_tag);

    crf_chunk<<<NCHUNK, NTAG * NTAG>>>(trans);

    crf_final<<<1, 256>>>(trans, tags, out);
}

// round 8
// speedup vs baseline: 1.7172x; 1.0617x over previous
#include <cuda_runtime.h>
#include <cuda_bf16.h>
#include <cstdint>

// ---------------- problem constants ----------------
#define SEQ   8192
#define EMB   768
#define HD    512          // per-direction hidden
#define G4    2048         // 4*HD
#define NTAG  14
#define START_IDX 12
#define STOP_IDX  13
#define NEGBIG (-1e30f)

#define REC_CTAS   128          // 64 per direction (exact R2 recurrence)
#define GEMM_CTAS  128          // persistent GEMM workers
#define NGRP       64           // 64 groups of 128 steps
#define NB_PER_GRP 16           // n-blocks per (dir, m-tile)
#define CHUNK  64               // CRF chunk length
#define NCHUNK (SEQ / CHUNK)    // 128

// ---------------- device scratch (static; no allocations) ----------------
__device__ float    g_xg[2][SEQ * G4];          // gate-interleaved [t][dim][gate]
__device__ float    g_hs[2][SEQ * HD];          // hidden states (for feats)
__device__ float    g_feats[SEQ * NTAG];
__device__ float    g_hbuf[2][2][HD];           // [dir][buf][dim]
__device__ unsigned g_bar[2][32];               // per-direction counter (128B apart)
__device__ unsigned g_done[2][NGRP];            // per-(dir,group) completed n-blocks
__device__ float    g_chunkM[NCHUNK][NTAG][NTAG];

// ---------------- helpers ----------------
__device__ __forceinline__ float sigf(float x) {
    return __fdividef(1.0f, 1.0f + __expf(-x));
}
__device__ __forceinline__ float tanh_fast(float x) {
    float a = fabsf(x);
    float e = __expf(-2.0f * a);                 // in (0,1], never overflows
    float t = __fdividef(1.0f - e, 1.0f + e);
    return copysignf(t, x);
}

// =====================================================================
// init: h0 into buffers, reset counters (runs every launch/replay)
// =====================================================================
__global__ void init_state(const float* __restrict__ h0)
{
    int i = threadIdx.x;                         // 512 threads
    g_hbuf[0][0][i] = h0[i];
    g_hbuf[1][0][i] = h0[HD + i];
    if (i < 2) g_bar[i][0] = 0u;
    if (i < 2 * NGRP) g_done[i >> 6][i & 63] = 0u;
}

// =====================================================================
// Fused persistent kernel:
//   blockIdx <  REC_CTAS : BiLSTM recurrence (exact R2 micro-structure)
//   blockIdx >= REC_CTAS : GEMM worker producing xg tiles in consume order
// =====================================================================
#define BM 128
#define BN 128
#define BK 16
#define SH_FLOATS (2 * BK * (BM + 4))            // As + Bs = 4224 floats

__device__ __forceinline__ void gemm_worker(
    float* sh, int worker,
    const float* __restrict__ emb,
    const float* __restrict__ wih_f, const float* __restrict__ bih_f, const float* __restrict__ bhh_f,
    const float* __restrict__ wih_b, const float* __restrict__ bih_b, const float* __restrict__ bhh_b)
{
    float (*As)[BM + 4] = (float (*)[BM + 4])sh;
    float (*Bs)[BN + 4] = (float (*)[BN + 4])(sh + BK * (BM + 4));

    const int tx = threadIdx.x;                  // 0..255
    const int tm = (tx >> 4) * 8;
    const int tn = (tx & 15) * 8;
    const int r0  = tx >> 2,          c40 = (tx & 3) * 4;
    const int r1  = (tx + 256) >> 2,  c41 = ((tx + 256) & 3) * 4;

    // tiles ordered by consumption: idx = grp*32 + dir*16 + nb
    for (int tile = worker; tile < NGRP * 32; tile += GEMM_CTAS) {
        const int grp = tile >> 5;
        const int rem = tile & 31;
        const int dir = rem >> 4;
        const int nb  = rem & 15;
        const int mtile = dir ? (NGRP - 1 - grp) : grp;

        const float* __restrict__ W  = dir ? wih_b : wih_f;
        const float* __restrict__ b1 = dir ? bih_b : bih_f;
        const float* __restrict__ b2 = dir ? bhh_b : bhh_f;
        float* __restrict__ out = g_xg[dir];

        const int m0 = mtile * BM;
        const int n0 = nb * BN;

        float acc[8][8] = {};

        float4 pa0 = *(const float4*)&emb[(m0 + r0) * EMB + c40];
        float4 pa1 = *(const float4*)&emb[(m0 + r1) * EMB + c41];
        float4 pb0 = *(const float4*)&W  [(n0 + r0) * EMB + c40];
        float4 pb1 = *(const float4*)&W  [(n0 + r1) * EMB + c41];

        for (int k0 = 0; k0 < EMB; k0 += BK) {
            As[c40 + 0][r0] = pa0.x; As[c40 + 1][r0] = pa0.y;
            As[c40 + 2][r0] = pa0.z; As[c40 + 3][r0] = pa0.w;
            As[c41 + 0][r1] = pa1.x; As[c41 + 1][r1] = pa1.y;
            As[c41 + 2][r1] = pa1.z; As[c41 + 3][r1] = pa1.w;
            Bs[c40 + 0][r0] = pb0.x; Bs[c40 + 1][r0] = pb0.y;
            Bs[c40 + 2][r0] = pb0.z; Bs[c40 + 3][r0] = pb0.w;
            Bs[c41 + 0][r1] = pb1.x; Bs[c41 + 1][r1] = pb1.y;
            Bs[c41 + 2][r1] = pb1.z; Bs[c41 + 3][r1] = pb1.w;
            __syncthreads();

            if (k0 + BK < EMB) {
                const int kn = k0 + BK;
                pa0 = *(const float4*)&emb[(m0 + r0) * EMB + kn + c40];
                pa1 = *(const float4*)&emb[(m0 + r1) * EMB + kn + c41];
                pb0 = *(const float4*)&W  [(n0 + r0) * EMB + kn + c40];
                pb1 = *(const float4*)&W  [(n0 + r1) * EMB + kn + c41];
            }

            #pragma unroll
            for (int kk = 0; kk < BK; kk++) {
                float a[8], b[8];
                #pragma unroll
                for (int i = 0; i < 8; i++) a[i] = As[kk][tm + i];
                #pragma unroll
                for (int j = 0; j < 8; j++) b[j] = Bs[kk][tn + j];
                #pragma unroll
                for (int i = 0; i < 8; i++)
                    #pragma unroll
                    for (int j = 0; j < 8; j++)
                        acc[i][j] = fmaf(a[i], b[j], acc[i][j]);
            }
            __syncthreads();
        }

        // store, gate-interleaved: row r -> [t*2048 + (r&511)*4 + (r>>9)]
        #pragma unroll
        for (int i = 0; i < 8; i++) {
            int t = m0 + tm + i;
            #pragma unroll
            for (int j = 0; j < 8; j++) {
                int r = n0 + tn + j;
                out[t * G4 + ((r & (HD - 1)) << 2) + (r >> 9)] = acc[i][j] + b1[r] + b2[r];
            }
        }

        __syncthreads();                         // all threads' stores happen-before fence
        if (threadIdx.x == 0) {
            __threadfence();
            atomicAdd(&g_done[dir][grp], 1u);
        }
        __syncthreads();
    }
}

__device__ __forceinline__ void wait_group(int dir, int grp)
{
    if (threadIdx.x == 0) {
        volatile unsigned* dp = &g_done[dir][grp];
        while (*dp < (unsigned)NB_PER_GRP) { }
    }
    __syncthreads();
}

__device__ __forceinline__ void rec_body(
    float* sh,
    const float* __restrict__ whh_f,
    const float* __restrict__ whh_b,
    const float* __restrict__ c0)
{
    const int dir = blockIdx.x >> 6;             // 64 blocks per direction
    const int blk = blockIdx.x & 63;
    const int w   = threadIdx.x >> 5;            // warp 0..7
    const int l   = threadIdx.x & 31;
    const int j   = blk * 8 + w;                 // owned h-dim

    const float* __restrict__ W  = dir ? whh_b : whh_f;
    const float* __restrict__ xg = g_xg[dir];
    float* __restrict__ hs = g_hs[dir];
    float* hb0 = g_hbuf[dir][0];
    float* hb1 = g_hbuf[dir][1];
    unsigned* bar = &g_bar[dir][0];

    // weights register-resident; lane l covers k = l, l+32, ..., l+480
    float wr[4][16];
    #pragma unroll
    for (int g = 0; g < 4; g++) {
        const float* wrow = &W[(g * HD + j) * HD];
        #pragma unroll
        for (int kk = 0; kk < 16; kk++) wr[g][kk] = wrow[kk * 32 + l];
    }
    float c = c0[dir * HD + j];

    float* hsh = sh;                             // 512 floats of the shared union

    // stage initial h (2 floats / thread)
    {
        float2 v = __ldcg((const float2*)&hb0[threadIdx.x * 2]);
        hsh[threadIdx.x * 2 + 0] = v.x;
        hsh[threadIdx.x * 2 + 1] = v.y;
    }
    __syncthreads();

    // wait for the first xg group of this direction, then prefetch step 0
    wait_group(dir, 0);
    int s0 = dir ? (SEQ - 1) : 0;
    float4 xv = *(const float4*)&xg[s0 * G4 + j * 4];

    for (int grp = 0; grp < NGRP; grp++) {
        const int tbase = grp * 128;
        for (int ti = 0; ti < 128; ti++) {
            const int t = tbase + ti;
            const int s = dir ? (SEQ - 1 - t) : t;

            // prefetch next step's xg (within-group only; boundary handled below)
            float4 xv_next;
            const bool have_next = (ti + 1 < 128);
            if (have_next) {
                int sn = dir ? (SEQ - 2 - t) : (t + 1);
                xv_next = *(const float4*)&xg[sn * G4 + j * 4];
            }

            // h chunk from smem
            float h[16];
            #pragma unroll
            for (int kk = 0; kk < 16; kk++) h[kk] = hsh[kk * 32 + l];

            float d0 = 0.f, d1 = 0.f, d2 = 0.f, d3 = 0.f;
            #pragma unroll
            for (int kk = 0; kk < 16; kk++) {
                d0 = fmaf(wr[0][kk], h[kk], d0);
                d1 = fmaf(wr[1][kk], h[kk], d1);
                d2 = fmaf(wr[2][kk], h[kk], d2);
                d3 = fmaf(wr[3][kk], h[kk], d3);
            }
            #pragma unroll
            for (int off = 16; off > 0; off >>= 1) {
                d0 += __shfl_down_sync(0xffffffffu, d0, off);
                d1 += __shfl_down_sync(0xffffffffu, d1, off);
                d2 += __shfl_down_sync(0xffffffffu, d2, off);
                d3 += __shfl_down_sync(0xffffffffu, d3, off);
            }

            float* hdst = (t & 1) ? hb0 : hb1;
            if (l == 0) {
                float gi = xv.x + d0;
                float gf = xv.y + d1;
                float gg = xv.z + d2;
                float go = xv.w + d3;
                c = sigf(gf) * c + sigf(gi) * tanh_fast(gg);
                float hn = sigf(go) * tanh_fast(c);
                __stcg(&hdst[j], hn);            // L2-visible for other SMs
                hs[s * HD + j] = hn;
            }
            if (have_next) xv = xv_next;

            __syncthreads();                      // block's h stores done
            if (threadIdx.x == 0) {
                __threadfence();
                atomicAdd(bar, 1u);
                const unsigned target = (unsigned)(REC_CTAS / 2) * (unsigned)(t + 1);
                while (*(volatile unsigned*)bar < target) { }
            }
            __syncthreads();

            // stage the just-produced h for the next step
            if (t + 1 < SEQ) {
                const float* hsrc = (t & 1) ? hb0 : hb1;
                float2 v = __ldcg((const float2*)&hsrc[threadIdx.x * 2]);
                hsh[threadIdx.x * 2 + 0] = v.x;
                hsh[threadIdx.x * 2 + 1] = v.y;
                __syncthreads();
            }
        }
        // group boundary: wait for next group's tile, then prefetch its first xg
        if (grp + 1 < NGRP) {
            wait_group(dir, grp + 1);
            const int tn = (grp + 1) * 128;
            const int sn = dir ? (SEQ - 1 - tn) : tn;
            xv = *(const float4*)&xg[sn * G4 + j * 4];
        }
    }
}

__global__ void __launch_bounds__(256, 2) fused_main(
    const float* __restrict__ emb,
    const float* __restrict__ wih_f, const float* __restrict__ bih_f, const float* __restrict__ bhh_f,
    const float* __restrict__ wih_b, const float* __restrict__ bih_b, const float* __restrict__ bhh_b,
    const float* __restrict__ whh_f, const float* __restrict__ whh_b,
    const float* __restrict__ c0)
{
    __shared__ float sh[SH_FLOATS];              // union: rec uses 512, gemm uses all
    if (blockIdx.x < REC_CTAS) {
        rec_body(sh, whh_f, whh_b, c0);
    } else {
        gemm_worker(sh, blockIdx.x - REC_CTAS,
                    emb, wih_f, bih_f, bhh_f, wih_b, bih_b, bhh_b);
    }
}

// =====================================================================
// feats[t, j] = [hs_f | hs_b] . w_tag[j] + b_tag[j]
// =====================================================================
__global__ void feats_kernel(const float* __restrict__ w_tag,
                             const float* __restrict__ b_tag)
{
    const int t = blockIdx.x;
    const int w = threadIdx.x >> 5;              // 0..13 (tag)
    const int l = threadIdx.x & 31;
    const float* __restrict__ hf = &g_hs[0][t * HD];
    const float* __restrict__ hb = &g_hs[1][t * HD];
    const float* __restrict__ wt = &w_tag[w * 1024];

    float acc = 0.f;
    #pragma unroll
    for (int k = l; k < HD; k += 32)
        acc = fmaf(hf[k], wt[k], fmaf(hb[k], wt[HD + k], acc));
    #pragma unroll
    for (int off = 16; off > 0; off >>= 1)
        acc += __shfl_down_sync(0xffffffffu, acc, off);
    if (l == 0) g_feats[t * NTAG + w] = acc + b_tag[w];
}

// =====================================================================
// CRF chunk matrices (log-semiring): Ms <- M_t (o) Ms, 64 steps/chunk
// =====================================================================
__global__ void crf_chunk(const float* __restrict__ trans)
{
    __shared__ float Ms[NTAG][NTAG + 2];
    const int tid = threadIdx.x;                 // 0..195
    const int j = tid / NTAG;
    const int i = tid % NTAG;

    float trow[NTAG];
    #pragma unroll
    for (int k = 0; k < NTAG; k++) trow[k] = trans[j * NTAG + k];

    Ms[j][i] = (i == j) ? 0.f : NEGBIG;          // semiring identity
    __syncthreads();

    const int base = blockIdx.x * CHUNK;
    for (int t = base; t < base + CHUNK; t++) {
        float fj = g_feats[t * NTAG + j];
        float vals[NTAG];
        float m = NEGBIG;
        #pragma unroll
        for (int k = 0; k < NTAG; k++) {
            vals[k] = trow[k] + Ms[k][i];
            m = fmaxf(m, vals[k]);
        }
        float s = 0.f;
        #pragma unroll
        for (int k = 0; k < NTAG; k++) s += __expf(vals[k] - m);
        float nv = m + __logf(s) + fj;
        __syncthreads();
        Ms[j][i] = nv;
        __syncthreads();
    }
    g_chunkM[blockIdx.x][j][i] = Ms[j][i];
}

// =====================================================================
// gold score (parallel reduce) + chunk composition + final output
// =====================================================================
__global__ void crf_final(const float* __restrict__ trans,
                          const int* __restrict__ tags,
                          float* __restrict__ out)
{
    __shared__ float red[256];
    const int tid = threadIdx.x;

    float part = 0.f;
    for (int t = tid; t < SEQ; t += 256) {
        int tag  = tags[t];
        int prev = (t == 0) ? START_IDX : tags[t - 1];
        part += g_feats[t * NTAG + tag] + trans[tag * NTAG + prev];
    }
    red[tid] = part;
    __syncthreads();
    #pragma unroll
    for (int s = 128; s > 0; s >>= 1) {
        if (tid < s) red[tid] += red[tid + s];
        __syncthreads();
    }
    const float gold = red[0] + trans[STOP_IDX * NTAG + tags[SEQ - 1]];

    if (tid < 32) {
        const int l = tid;
        float fv = (l < NTAG) ? ((l == START_IDX) ? 0.f : NEGBIG) : NEGBIG;
        for (int cix = 0; cix < NCHUNK; cix++) {
            float vals[NTAG];
            float m = NEGBIG;
            #pragma unroll
            for (int i = 0; i < NTAG; i++) {
                float fvi = __shfl_sync(0xffffffffu, fv, i);
                float v = (l < NTAG) ? (g_chunkM[cix][l][i] + fvi) : NEGBIG;
                vals[i] = v;
                m = fmaxf(m, v);
            }
            float s = 0.f;
            #pragma unroll
            for (int i = 0; i < NTAG; i++) s += __expf(vals[i] - m);
            float nv = m + __logf(s);
            fv = (l < NTAG) ? nv : NEGBIG;
        }
        float v = (l < NTAG) ? (fv + trans[STOP_IDX * NTAG + l]) : NEGBIG;
        float m = v;
        #pragma unroll
        for (int off = 16; off > 0; off >>= 1)
            m = fmaxf(m, __shfl_xor_sync(0xffffffffu, m, off));
        float e = __expf(v - m);
        #pragma unroll
        for (int off = 16; off > 0; off >>= 1)
            e += __shfl_xor_sync(0xffffffffu, e, off);
        float fwd = m + __logf(e);
        if (l == 0) out[0] = fwd - gold;
    }
}

// =====================================================================
// launch
// =====================================================================
extern "C" void kernel_launch(void* const* d_in, const int* in_sizes, int n_in,
                              void* d_out, int out_size)
{
    const float* embeds = (const float*)d_in[0];
    const int*   tags   = (const int*)  d_in[1];
    const float* w_ih_f = (const float*)d_in[2];
    const float* w_hh_f = (const float*)d_in[3];
    const float* b_ih_f = (const float*)d_in[4];
    const float* b_hh_f = (const float*)d_in[5];
    const float* w_ih_b = (const float*)d_in[6];
    const float* w_hh_b = (const float*)d_in[7];
    const float* b_ih_b = (const float*)d_in[8];
    const float* b_hh_b = (const float*)d_in[9];
    const float* w_tag  = (const float*)d_in[10];
    const float* b_tag  = (const float*)d_in[11];
    const float* trans  = (const float*)d_in[12];
    const float* h0     = (const float*)d_in[13];
    const float* c0     = (const float*)d_in[14];
    float* out = (float*)d_out;

    init_state<<<1, 512>>>(h0);

    fused_main<<<REC_CTAS + GEMM_CTAS, 256>>>(embeds,
                                              w_ih_f, b_ih_f, b_hh_f,
                                              w_ih_b, b_ih_b, b_hh_b,
                                              w_hh_f, w_hh_b, c0);

    feats_kernel<<<SEQ, NTAG * 32>>>(w_tag, b_tag);

    crf_chunk<<<NCHUNK, NTAG * NTAG>>>(trans);

    crf_final<<<1, 256>>>(trans, tags, out);
}

// round 9
// speedup vs baseline: 1.8760x; 1.0925x over previous
#include <cuda_runtime.h>
#include <cuda_bf16.h>
#include <cstdint>

// ---------------- problem constants ----------------
#define SEQ   8192
#define EMB   768
#define HD    512          // per-direction hidden
#define G4    2048         // 4*HD
#define NTAG  14
#define START_IDX 12
#define STOP_IDX  13
#define NEGBIG (-1e30f)

#define REC_CTAS   128          // 64 per direction (exact R2 recurrence)
#define GEMM_CTAS  24           // dedicated GEMM SMs; 128+24=152 = GB300 SM count
#define NGRP       64           // 64 groups of 128 steps
#define NB_PER_GRP 16           // n-blocks per (dir, m-tile)
#define CHUNK  64               // CRF chunk length
#define NCHUNK (SEQ / CHUNK)    // 128

// ---------------- device scratch (static; no allocations) ----------------
__device__ float    g_xg[2][SEQ * G4];          // gate-interleaved [t][dim][gate]
__device__ float    g_hs[2][SEQ * HD];          // hidden states (for feats)
__device__ float    g_feats[SEQ * NTAG];
__device__ float    g_hbuf[2][2][HD];           // [dir][buf][dim]
__device__ unsigned g_bar[2][32];               // per-direction counter (128B apart)
__device__ unsigned g_done[2][NGRP];            // per-(dir,group) completed n-blocks
__device__ float    g_chunkM[NCHUNK][NTAG][NTAG];

// ---------------- helpers ----------------
__device__ __forceinline__ float sigf(float x) {
    return __fdividef(1.0f, 1.0f + __expf(-x));
}
__device__ __forceinline__ float tanh_fast(float x) {
    float a = fabsf(x);
    float e = __expf(-2.0f * a);                 // in (0,1], never overflows
    float t = __fdividef(1.0f - e, 1.0f + e);
    return copysignf(t, x);
}

// =====================================================================
// init: h0 into buffers, reset counters (runs every launch/replay)
// =====================================================================
__global__ void init_state(const float* __restrict__ h0)
{
    int i = threadIdx.x;                         // 512 threads
    g_hbuf[0][0][i] = h0[i];
    g_hbuf[1][0][i] = h0[HD + i];
    if (i < 2) g_bar[i][0] = 0u;
    if (i < 2 * NGRP) g_done[i >> 6][i & 63] = 0u;
}

// =====================================================================
// Fused persistent kernel (one CTA per SM):
//   blockIdx <  REC_CTAS : BiLSTM recurrence (exact R2 micro-structure)
//   blockIdx >= REC_CTAS : GEMM worker producing xg tiles in consume order
// =====================================================================
#define BM 128
#define BN 128
#define BK 16
#define SH_FLOATS (2 * BK * (BM + 4))            // As + Bs = 4224 floats

__device__ __forceinline__ void gemm_worker(
    float* sh, int worker,
    const float* __restrict__ emb,
    const float* __restrict__ wih_f, const float* __restrict__ bih_f, const float* __restrict__ bhh_f,
    const float* __restrict__ wih_b, const float* __restrict__ bih_b, const float* __restrict__ bhh_b)
{
    float (*As)[BM + 4] = (float (*)[BM + 4])sh;
    float (*Bs)[BN + 4] = (float (*)[BN + 4])(sh + BK * (BM + 4));

    const int tx = threadIdx.x;                  // 0..255
    const int tm = (tx >> 4) * 8;
    const int tn = (tx & 15) * 8;
    const int r0  = tx >> 2,          c40 = (tx & 3) * 4;
    const int r1  = (tx + 256) >> 2,  c41 = ((tx + 256) & 3) * 4;

    // tiles ordered by consumption: idx = grp*32 + dir*16 + nb
    for (int tile = worker; tile < NGRP * 32; tile += GEMM_CTAS) {
        const int grp = tile >> 5;
        const int rem = tile & 31;
        const int dir = rem >> 4;
        const int nb  = rem & 15;
        const int mtile = dir ? (NGRP - 1 - grp) : grp;

        const float* __restrict__ W  = dir ? wih_b : wih_f;
        const float* __restrict__ b1 = dir ? bih_b : bih_f;
        const float* __restrict__ b2 = dir ? bhh_b : bhh_f;
        float* __restrict__ out = g_xg[dir];

        const int m0 = mtile * BM;
        const int n0 = nb * BN;

        float acc[8][8] = {};

        float4 pa0 = *(const float4*)&emb[(m0 + r0) * EMB + c40];
        float4 pa1 = *(const float4*)&emb[(m0 + r1) * EMB + c41];
        float4 pb0 = *(const float4*)&W  [(n0 + r0) * EMB + c40];
        float4 pb1 = *(const float4*)&W  [(n0 + r1) * EMB + c41];

        for (int k0 = 0; k0 < EMB; k0 += BK) {
            As[c40 + 0][r0] = pa0.x; As[c40 + 1][r0] = pa0.y;
            As[c40 + 2][r0] = pa0.z; As[c40 + 3][r0] = pa0.w;
            As[c41 + 0][r1] = pa1.x; As[c41 + 1][r1] = pa1.y;
            As[c41 + 2][r1] = pa1.z; As[c41 + 3][r1] = pa1.w;
            Bs[c40 + 0][r0] = pb0.x; Bs[c40 + 1][r0] = pb0.y;
            Bs[c40 + 2][r0] = pb0.z; Bs[c40 + 3][r0] = pb0.w;
            Bs[c41 + 0][r1] = pb1.x; Bs[c41 + 1][r1] = pb1.y;
            Bs[c41 + 2][r1] = pb1.z; Bs[c41 + 3][r1] = pb1.w;
            __syncthreads();

            if (k0 + BK < EMB) {
                const int kn = k0 + BK;
                pa0 = *(const float4*)&emb[(m0 + r0) * EMB + kn + c40];
                pa1 = *(const float4*)&emb[(m0 + r1) * EMB + kn + c41];
                pb0 = *(const float4*)&W  [(n0 + r0) * EMB + kn + c40];
                pb1 = *(const float4*)&W  [(n0 + r1) * EMB + kn + c41];
            }

            #pragma unroll
            for (int kk = 0; kk < BK; kk++) {
                float a[8], b[8];
                #pragma unroll
                for (int i = 0; i < 8; i++) a[i] = As[kk][tm + i];
                #pragma unroll
                for (int j = 0; j < 8; j++) b[j] = Bs[kk][tn + j];
                #pragma unroll
                for (int i = 0; i < 8; i++)
                    #pragma unroll
                    for (int j = 0; j < 8; j++)
                        acc[i][j] = fmaf(a[i], b[j], acc[i][j]);
            }
            __syncthreads();
        }

        // store, gate-interleaved: row r -> [t*2048 + (r&511)*4 + (r>>9)]
        #pragma unroll
        for (int i = 0; i < 8; i++) {
            int t = m0 + tm + i;
            #pragma unroll
            for (int j = 0; j < 8; j++) {
                int r = n0 + tn + j;
                out[t * G4 + ((r & (HD - 1)) << 2) + (r >> 9)] = acc[i][j] + b1[r] + b2[r];
            }
        }

        __syncthreads();                         // all threads' stores happen-before fence
        if (threadIdx.x == 0) {
            __threadfence();
            atomicAdd(&g_done[dir][grp], 1u);
        }
        __syncthreads();
    }
}

__device__ __forceinline__ void wait_group(int dir, int grp)
{
    if (threadIdx.x == 0) {
        volatile unsigned* dp = &g_done[dir][grp];
        while (*dp < (unsigned)NB_PER_GRP) { }
    }
    __syncthreads();
}

__device__ __forceinline__ void rec_body(
    float* sh,
    const float* __restrict__ whh_f,
    const float* __restrict__ whh_b,
    const float* __restrict__ c0)
{
    const int dir = blockIdx.x >> 6;             // 64 blocks per direction
    const int blk = blockIdx.x & 63;
    const int w   = threadIdx.x >> 5;            // warp 0..7
    const int l   = threadIdx.x & 31;
    const int j   = blk * 8 + w;                 // owned h-dim

    const float* __restrict__ W  = dir ? whh_b : whh_f;
    const float* __restrict__ xg = g_xg[dir];
    float* __restrict__ hs = g_hs[dir];
    float* hb0 = g_hbuf[dir][0];
    float* hb1 = g_hbuf[dir][1];
    unsigned* bar = &g_bar[dir][0];

    // weights register-resident; lane l covers k = l, l+32, ..., l+480
    float wr[4][16];
    #pragma unroll
    for (int g = 0; g < 4; g++) {
        const float* wrow = &W[(g * HD + j) * HD];
        #pragma unroll
        for (int kk = 0; kk < 16; kk++) wr[g][kk] = wrow[kk * 32 + l];
    }
    float c = c0[dir * HD + j];

    float* hsh = sh;                             // 512 floats of the shared union

    // stage initial h (2 floats / thread)
    {
        float2 v = __ldcg((const float2*)&hb0[threadIdx.x * 2]);
        hsh[threadIdx.x * 2 + 0] = v.x;
        hsh[threadIdx.x * 2 + 1] = v.y;
    }
    __syncthreads();

    // wait for the first xg group of this direction, then prefetch step 0
    wait_group(dir, 0);
    int s0 = dir ? (SEQ - 1) : 0;
    float4 xv = *(const float4*)&xg[s0 * G4 + j * 4];

    for (int grp = 0; grp < NGRP; grp++) {
        const int tbase = grp * 128;
        for (int ti = 0; ti < 128; ti++) {
            const int t = tbase + ti;
            const int s = dir ? (SEQ - 1 - t) : t;

            // prefetch next step's xg (within-group only; boundary handled below)
            float4 xv_next;
            const bool have_next = (ti + 1 < 128);
            if (have_next) {
                int sn = dir ? (SEQ - 2 - t) : (t + 1);
                xv_next = *(const float4*)&xg[sn * G4 + j * 4];
            }

            // h chunk from smem
            float h[16];
            #pragma unroll
            for (int kk = 0; kk < 16; kk++) h[kk] = hsh[kk * 32 + l];

            float d0 = 0.f, d1 = 0.f, d2 = 0.f, d3 = 0.f;
            #pragma unroll
            for (int kk = 0; kk < 16; kk++) {
                d0 = fmaf(wr[0][kk], h[kk], d0);
                d1 = fmaf(wr[1][kk], h[kk], d1);
                d2 = fmaf(wr[2][kk], h[kk], d2);
                d3 = fmaf(wr[3][kk], h[kk], d3);
            }
            #pragma unroll
            for (int off = 16; off > 0; off >>= 1) {
                d0 += __shfl_down_sync(0xffffffffu, d0, off);
                d1 += __shfl_down_sync(0xffffffffu, d1, off);
                d2 += __shfl_down_sync(0xffffffffu, d2, off);
                d3 += __shfl_down_sync(0xffffffffu, d3, off);
            }

            float* hdst = (t & 1) ? hb0 : hb1;
            if (l == 0) {
                float gi = xv.x + d0;
                float gf = xv.y + d1;
                float gg = xv.z + d2;
                float go = xv.w + d3;
                c = sigf(gf) * c + sigf(gi) * tanh_fast(gg);
                float hn = sigf(go) * tanh_fast(c);
                __stcg(&hdst[j], hn);            // L2-visible for other SMs
                hs[s * HD + j] = hn;
            }
            if (have_next) xv = xv_next;

            __syncthreads();                      // block's h stores done
            if (threadIdx.x == 0) {
                __threadfence();
                atomicAdd(bar, 1u);
                const unsigned target = (unsigned)(REC_CTAS / 2) * (unsigned)(t + 1);
                while (*(volatile unsigned*)bar < target) { }
            }
            __syncthreads();

            // stage the just-produced h for the next step
            if (t + 1 < SEQ) {
                const float* hsrc = (t & 1) ? hb0 : hb1;
                float2 v = __ldcg((const float2*)&hsrc[threadIdx.x * 2]);
                hsh[threadIdx.x * 2 + 0] = v.x;
                hsh[threadIdx.x * 2 + 1] = v.y;
                __syncthreads();
            }
        }
        // group boundary: wait for next group's tile, then prefetch its first xg
        if (grp + 1 < NGRP) {
            wait_group(dir, grp + 1);
            const int tn = (grp + 1) * 128;
            const int sn = dir ? (SEQ - 1 - tn) : tn;
            xv = *(const float4*)&xg[sn * G4 + j * 4];
        }
    }
}

__global__ void __launch_bounds__(256, 1) fused_main(
    const float* __restrict__ emb,
    const float* __restrict__ wih_f, const float* __restrict__ bih_f, const float* __restrict__ bhh_f,
    const float* __restrict__ wih_b, const float* __restrict__ bih_b, const float* __restrict__ bhh_b,
    const float* __restrict__ whh_f, const float* __restrict__ whh_b,
    const float* __restrict__ c0)
{
    __shared__ float sh[SH_FLOATS];              // union: rec uses 512, gemm uses all
    if (blockIdx.x < REC_CTAS) {
        rec_body(sh, whh_f, whh_b, c0);
    } else {
        gemm_worker(sh, blockIdx.x - REC_CTAS,
                    emb, wih_f, bih_f, bhh_f, wih_b, bih_b, bhh_b);
    }
}

// =====================================================================
// feats[t, j] = [hs_f | hs_b] . w_tag[j] + b_tag[j]
// =====================================================================
__global__ void feats_kernel(const float* __restrict__ w_tag,
                             const float* __restrict__ b_tag)
{
    const int t = blockIdx.x;
    const int w = threadIdx.x >> 5;              // 0..13 (tag)
    const int l = threadIdx.x & 31;
    const float* __restrict__ hf = &g_hs[0][t * HD];
    const float* __restrict__ hb = &g_hs[1][t * HD];
    const float* __restrict__ wt = &w_tag[w * 1024];

    float acc = 0.f;
    #pragma unroll
    for (int k = l; k < HD; k += 32)
        acc = fmaf(hf[k], wt[k], fmaf(hb[k], wt[HD + k], acc));
    #pragma unroll
    for (int off = 16; off > 0; off >>= 1)
        acc += __shfl_down_sync(0xffffffffu, acc, off);
    if (l == 0) g_feats[t * NTAG + w] = acc + b_tag[w];
}

// =====================================================================
// CRF chunk matrices (log-semiring): Ms <- M_t (o) Ms, 64 steps/chunk
// =====================================================================
__global__ void crf_chunk(const float* __restrict__ trans)
{
    __shared__ float Ms[NTAG][NTAG + 2];
    const int tid = threadIdx.x;                 // 0..195
    const int j = tid / NTAG;
    const int i = tid % NTAG;

    float trow[NTAG];
    #pragma unroll
    for (int k = 0; k < NTAG; k++) trow[k] = trans[j * NTAG + k];

    Ms[j][i] = (i == j) ? 0.f : NEGBIG;          // semiring identity
    __syncthreads();

    const int base = blockIdx.x * CHUNK;
    for (int t = base; t < base + CHUNK; t++) {
        float fj = g_feats[t * NTAG + j];
        float vals[NTAG];
        float m = NEGBIG;
        #pragma unroll
        for (int k = 0; k < NTAG; k++) {
            vals[k] = trow[k] + Ms[k][i];
            m = fmaxf(m, vals[k]);
        }
        float s = 0.f;
        #pragma unroll
        for (int k = 0; k < NTAG; k++) s += __expf(vals[k] - m);
        float nv = m + __logf(s) + fj;
        __syncthreads();
        Ms[j][i] = nv;
        __syncthreads();
    }
    g_chunkM[blockIdx.x][j][i] = Ms[j][i];
}

// =====================================================================
// gold score (parallel reduce) + chunk composition + final output
// =====================================================================
__global__ void crf_final(const float* __restrict__ trans,
                          const int* __restrict__ tags,
                          float* __restrict__ out)
{
    __shared__ float red[256];
    const int tid = threadIdx.x;

    float part = 0.f;
    for (int t = tid; t < SEQ; t += 256) {
        int tag  = tags[t];
        int prev = (t == 0) ? START_IDX : tags[t - 1];
        part += g_feats[t * NTAG + tag] + trans[tag * NTAG + prev];
    }
    red[tid] = part;
    __syncthreads();
    #pragma unroll
    for (int s = 128; s > 0; s >>= 1) {
        if (tid < s) red[tid] += red[tid + s];
        __syncthreads();
    }
    const float gold = red[0] + trans[STOP_IDX * NTAG + tags[SEQ - 1]];

    if (tid < 32) {
        const int l = tid;
        float fv = (l < NTAG) ? ((l == START_IDX) ? 0.f : NEGBIG) : NEGBIG;
        for (int cix = 0; cix < NCHUNK; cix++) {
            float vals[NTAG];
            float m = NEGBIG;
            #pragma unroll
            for (int i = 0; i < NTAG; i++) {
                float fvi = __shfl_sync(0xffffffffu, fv, i);
                float v = (l < NTAG) ? (g_chunkM[cix][l][i] + fvi) : NEGBIG;
                vals[i] = v;
                m = fmaxf(m, v);
            }
            float s = 0.f;
            #pragma unroll
            for (int i = 0; i < NTAG; i++) s += __expf(vals[i] - m);
            float nv = m + __logf(s);
            fv = (l < NTAG) ? nv : NEGBIG;
        }
        float v = (l < NTAG) ? (fv + trans[STOP_IDX * NTAG + l]) : NEGBIG;
        float m = v;
        #pragma unroll
        for (int off = 16; off > 0; off >>= 1)
            m = fmaxf(m, __shfl_xor_sync(0xffffffffu, m, off));
        float e = __expf(v - m);
        #pragma unroll
        for (int off = 16; off > 0; off >>= 1)
            e += __shfl_xor_sync(0xffffffffu, e, off);
        float fwd = m + __logf(e);
        if (l == 0) out[0] = fwd - gold;
    }
}

// =====================================================================
// launch
// =====================================================================
extern "C" void kernel_launch(void* const* d_in, const int* in_sizes, int n_in,
                              void* d_out, int out_size)
{
    const float* embeds = (const float*)d_in[0];
    const int*   tags   = (const int*)  d_in[1];
    const float* w_ih_f = (const float*)d_in[2];
    const float* w_hh_f = (const float*)d_in[3];
    const float* b_ih_f = (const float*)d_in[4];
    const float* b_hh_f = (const float*)d_in[5];
    const float* w_ih_b = (const float*)d_in[6];
    const float* w_hh_b = (const float*)d_in[7];
    const float* b_ih_b = (const float*)d_in[8];
    const float* b_hh_b = (const float*)d_in[9];
    const float* w_tag  = (const float*)d_in[10];
    const float* b_tag  = (const float*)d_in[11];
    const float* trans  = (const float*)d_in[12];
    const float* h0     = (const float*)d_in[13];
    const float* c0     = (const float*)d_in[14];
    float* out = (float*)d_out;

    init_state<<<1, 512>>>(h0);

    // 152 CTAs = GB300 SM count -> wave-1 places one CTA per SM (no sharing)
    fused_main<<<REC_CTAS + GEMM_CTAS, 256>>>(embeds,
                                              w_ih_f, b_ih_f, b_hh_f,
                                              w_ih_b, b_ih_b, b_hh_b,
                                              w_hh_f, w_hh_b, c0);

    feats_kernel<<<SEQ, NTAG * 32>>>(w_tag, b_tag);

    crf_chunk<<<NCHUNK, NTAG * NTAG>>>(trans);

    crf_final<<<1, 256>>>(trans, tags, out);
}

// round 10
// speedup vs baseline: 1.9130x; 1.0197x over previous
#include <cuda_runtime.h>
#include <cuda_bf16.h>
#include <cstdint>

// ---------------- problem constants ----------------
#define SEQ   8192
#define EMB   768
#define HD    512          // per-direction hidden
#define G4    2048         // 4*HD
#define NTAG  14
#define START_IDX 12
#define STOP_IDX  13
#define NEGBIG (-1e30f)

#define GRID_CTAS  152          // = GB300 SM count
#define REC_CTAS   128          // 64 per direction (exact R2 recurrence)
#define GEMM_CTAS  24           // dedicated GEMM SMs after phase A
#define NGRP       64           // 64 groups of 128 steps
#define NB_PER_GRP 16           // n-blocks per (dir, m-tile)
#define TOTAL_TILES (NGRP * 32) // 2048
#define PREF_TILES  304         // phase A: 2 rounds x 152 CTAs (~9.5 groups)
#define CHUNK  64               // CRF chunk length
#define NCHUNK (SEQ / CHUNK)    // 128

// ---------------- device scratch (static; no allocations) ----------------
__device__ float    g_xg[2][SEQ * G4];          // gate-interleaved [t][dim][gate]
__device__ float    g_hs[2][SEQ * HD];          // hidden states (for feats)
__device__ float    g_feats[SEQ * NTAG];
__device__ float    g_hbuf[2][2][HD];           // [dir][buf][dim]
__device__ unsigned g_bar[2][32];               // per-direction counter (128B apart)
__device__ unsigned g_done[2][NGRP];            // per-(dir,group) completed n-blocks
__device__ float    g_chunkM[NCHUNK][NTAG][NTAG];

// ---------------- helpers ----------------
__device__ __forceinline__ float sigf(float x) {
    return __fdividef(1.0f, 1.0f + __expf(-x));
}
__device__ __forceinline__ float tanh_fast(float x) {
    float a = fabsf(x);
    float e = __expf(-2.0f * a);                 // in (0,1], never overflows
    float t = __fdividef(1.0f - e, 1.0f + e);
    return copysignf(t, x);
}

// =====================================================================
// init: h0 into buffers, reset counters (runs every launch/replay)
// =====================================================================
__global__ void init_state(const float* __restrict__ h0)
{
    int i = threadIdx.x;                         // 512 threads
    g_hbuf[0][0][i] = h0[i];
    g_hbuf[1][0][i] = h0[HD + i];
    if (i < 2) g_bar[i][0] = 0u;
    if (i < 2 * NGRP) g_done[i >> 6][i & 63] = 0u;
}

// =====================================================================
// GEMM tile (double-buffered smem, one barrier per k-iter)
// =====================================================================
#define BM 128
#define BN 128
#define BK 16
#define STAGE_FLOATS (BK * (BM + 4) + BK * (BN + 4))   // 4224
#define SH_FLOATS    (2 * STAGE_FLOATS)                // 8448 floats = 33792 B

__device__ __forceinline__ void gemm_tile(
    float* sh, int tile,
    const float* __restrict__ emb,
    const float* __restrict__ wih_f, const float* __restrict__ bih_f, const float* __restrict__ bhh_f,
    const float* __restrict__ wih_b, const float* __restrict__ bih_b, const float* __restrict__ bhh_b)
{
    const int grp = tile >> 5;
    const int rem = tile & 31;
    const int dir = rem >> 4;
    const int nb  = rem & 15;
    const int mtile = dir ? (NGRP - 1 - grp) : grp;

    const float* __restrict__ W  = dir ? wih_b : wih_f;
    const float* __restrict__ b1 = dir ? bih_b : bih_f;
    const float* __restrict__ b2 = dir ? bhh_b : bhh_f;
    float* __restrict__ out = g_xg[dir];

    const int m0 = mtile * BM;
    const int n0 = nb * BN;

    const int tx = threadIdx.x;                  // 0..255
    const int tm = (tx >> 4) * 8;
    const int tn = (tx & 15) * 8;
    const int r0  = tx >> 2,          c40 = (tx & 3) * 4;
    const int r1  = (tx + 256) >> 2,  c41 = ((tx + 256) & 3) * 4;

    float (*As[2])[BM + 4];
    float (*Bs[2])[BN + 4];
    As[0] = (float (*)[BM + 4])sh;
    Bs[0] = (float (*)[BN + 4])(sh + BK * (BM + 4));
    As[1] = (float (*)[BM + 4])(sh + STAGE_FLOATS);
    Bs[1] = (float (*)[BN + 4])(sh + STAGE_FLOATS + BK * (BM + 4));

    float acc[8][8] = {};

    // prologue: load k=0 tile, commit to stage 0
    float4 pa0 = *(const float4*)&emb[(m0 + r0) * EMB + c40];
    float4 pa1 = *(const float4*)&emb[(m0 + r1) * EMB + c41];
    float4 pb0 = *(const float4*)&W  [(n0 + r0) * EMB + c40];
    float4 pb1 = *(const float4*)&W  [(n0 + r1) * EMB + c41];
    As[0][c40 + 0][r0] = pa0.x; As[0][c40 + 1][r0] = pa0.y;
    As[0][c40 + 2][r0] = pa0.z; As[0][c40 + 3][r0] = pa0.w;
    As[0][c41 + 0][r1] = pa1.x; As[0][c41 + 1][r1] = pa1.y;
    As[0][c41 + 2][r1] = pa1.z; As[0][c41 + 3][r1] = pa1.w;
    Bs[0][c40 + 0][r0] = pb0.x; Bs[0][c40 + 1][r0] = pb0.y;
    Bs[0][c40 + 2][r0] = pb0.z; Bs[0][c40 + 3][r0] = pb0.w;
    Bs[0][c41 + 0][r1] = pb1.x; Bs[0][c41 + 1][r1] = pb1.y;
    Bs[0][c41 + 2][r1] = pb1.z; Bs[0][c41 + 3][r1] = pb1.w;
    __syncthreads();

    const int NK = EMB / BK;                     // 48
    for (int ki = 0; ki < NK; ki++) {
        const int cur = ki & 1;
        const bool more = (ki + 1 < NK);
        if (more) {
            const int kn = (ki + 1) * BK;
            pa0 = *(const float4*)&emb[(m0 + r0) * EMB + kn + c40];
            pa1 = *(const float4*)&emb[(m0 + r1) * EMB + kn + c41];
            pb0 = *(const float4*)&W  [(n0 + r0) * EMB + kn + c40];
            pb1 = *(const float4*)&W  [(n0 + r1) * EMB + kn + c41];
        }

        float (*Ac)[BM + 4] = As[cur];
        float (*Bc)[BN + 4] = Bs[cur];
        #pragma unroll
        for (int kk = 0; kk < BK; kk++) {
            float a[8], b[8];
            #pragma unroll
            for (int i = 0; i < 8; i++) a[i] = Ac[kk][tm + i];
            #pragma unroll
            for (int j = 0; j < 8; j++) b[j] = Bc[kk][tn + j];
            #pragma unroll
            for (int i = 0; i < 8; i++)
                #pragma unroll
                for (int j = 0; j < 8; j++)
                    acc[i][j] = fmaf(a[i], b[j], acc[i][j]);
        }

        if (more) {
            const int nxt = cur ^ 1;
            As[nxt][c40 + 0][r0] = pa0.x; As[nxt][c40 + 1][r0] = pa0.y;
            As[nxt][c40 + 2][r0] = pa0.z; As[nxt][c40 + 3][r0] = pa0.w;
            As[nxt][c41 + 0][r1] = pa1.x; As[nxt][c41 + 1][r1] = pa1.y;
            As[nxt][c41 + 2][r1] = pa1.z; As[nxt][c41 + 3][r1] = pa1.w;
            Bs[nxt][c40 + 0][r0] = pb0.x; Bs[nxt][c40 + 1][r0] = pb0.y;
            Bs[nxt][c40 + 2][r0] = pb0.z; Bs[nxt][c40 + 3][r0] = pb0.w;
            Bs[nxt][c41 + 0][r1] = pb1.x; Bs[nxt][c41 + 1][r1] = pb1.y;
            Bs[nxt][c41 + 2][r1] = pb1.z; Bs[nxt][c41 + 3][r1] = pb1.w;
            __syncthreads();                     // one barrier per k-iter
        }
    }

    // store, gate-interleaved: row r -> [t*2048 + (r&511)*4 + (r>>9)]
    #pragma unroll
    for (int i = 0; i < 8; i++) {
        int t = m0 + tm + i;
        #pragma unroll
        for (int j = 0; j < 8; j++) {
            int r = n0 + tn + j;
            out[t * G4 + ((r & (HD - 1)) << 2) + (r >> 9)] = acc[i][j] + b1[r] + b2[r];
        }
    }

    __syncthreads();                             // all threads' stores precede fence
    if (threadIdx.x == 0) {
        __threadfence();
        atomicAdd(&g_done[dir][grp], 1u);
    }
    __syncthreads();
}

// =====================================================================
// recurrence support
// =====================================================================
__device__ __forceinline__ void wait_group(int dir, int grp)
{
    if (threadIdx.x == 0) {
        volatile unsigned* dp = &g_done[dir][grp];
        while (*dp < (unsigned)NB_PER_GRP) { }
    }
    __syncthreads();
}

__device__ __forceinline__ void rec_body(
    float* sh,
    const float* __restrict__ whh_f,
    const float* __restrict__ whh_b,
    const float* __restrict__ c0)
{
    const int dir = blockIdx.x >> 6;             // 64 blocks per direction
    const int blk = blockIdx.x & 63;
    const int w   = threadIdx.x >> 5;            // warp 0..7
    const int l   = threadIdx.x & 31;
    const int j   = blk * 8 + w;                 // owned h-dim

    const float* __restrict__ W  = dir ? whh_b : whh_f;
    const float* __restrict__ xg = g_xg[dir];
    float* __restrict__ hs = g_hs[dir];
    float* hb0 = g_hbuf[dir][0];
    float* hb1 = g_hbuf[dir][1];
    unsigned* bar = &g_bar[dir][0];

    // weights register-resident; lane l covers k = l, l+32, ..., l+480
    float wr[4][16];
    #pragma unroll
    for (int g = 0; g < 4; g++) {
        const float* wrow = &W[(g * HD + j) * HD];
        #pragma unroll
        for (int kk = 0; kk < 16; kk++) wr[g][kk] = wrow[kk * 32 + l];
    }
    float c = c0[dir * HD + j];

    float* hsh = sh;                             // 512 floats of the shared union

    // stage initial h (2 floats / thread)
    {
        float2 v = __ldcg((const float2*)&hb0[threadIdx.x * 2]);
        hsh[threadIdx.x * 2 + 0] = v.x;
        hsh[threadIdx.x * 2 + 1] = v.y;
    }
    __syncthreads();

    // wait for the first xg group of this direction, then prefetch step 0
    wait_group(dir, 0);
    int s0 = dir ? (SEQ - 1) : 0;
    float4 xv = *(const float4*)&xg[s0 * G4 + j * 4];

    for (int grp = 0; grp < NGRP; grp++) {
        const int tbase = grp * 128;
        for (int ti = 0; ti < 128; ti++) {
            const int t = tbase + ti;
            const int s = dir ? (SEQ - 1 - t) : t;

            // prefetch next step's xg (within-group only; boundary handled below)
            float4 xv_next;
            const bool have_next = (ti + 1 < 128);
            if (have_next) {
                int sn = dir ? (SEQ - 2 - t) : (t + 1);
                xv_next = *(const float4*)&xg[sn * G4 + j * 4];
            }

            // h chunk from smem
            float h[16];
            #pragma unroll
            for (int kk = 0; kk < 16; kk++) h[kk] = hsh[kk * 32 + l];

            float d0 = 0.f, d1 = 0.f, d2 = 0.f, d3 = 0.f;
            #pragma unroll
            for (int kk = 0; kk < 16; kk++) {
                d0 = fmaf(wr[0][kk], h[kk], d0);
                d1 = fmaf(wr[1][kk], h[kk], d1);
                d2 = fmaf(wr[2][kk], h[kk], d2);
                d3 = fmaf(wr[3][kk], h[kk], d3);
            }
            #pragma unroll
            for (int off = 16; off > 0; off >>= 1) {
                d0 += __shfl_down_sync(0xffffffffu, d0, off);
                d1 += __shfl_down_sync(0xffffffffu, d1, off);
                d2 += __shfl_down_sync(0xffffffffu, d2, off);
                d3 += __shfl_down_sync(0xffffffffu, d3, off);
            }

            float* hdst = (t & 1) ? hb0 : hb1;
            if (l == 0) {
                float gi = xv.x + d0;
                float gf = xv.y + d1;
                float gg = xv.z + d2;
                float go = xv.w + d3;
                c = sigf(gf) * c + sigf(gi) * tanh_fast(gg);
                float hn = sigf(go) * tanh_fast(c);
                __stcg(&hdst[j], hn);            // L2-visible for other SMs
                hs[s * HD + j] = hn;
            }
            if (have_next) xv = xv_next;

            __syncthreads();                      // block's h stores done
            if (threadIdx.x == 0) {
                __threadfence();
                atomicAdd(bar, 1u);
                const unsigned target = (unsigned)(REC_CTAS / 2) * (unsigned)(t + 1);
                while (*(volatile unsigned*)bar < target) { }
            }
            __syncthreads();

            // stage the just-produced h for the next step
            if (t + 1 < SEQ) {
                const float* hsrc = (t & 1) ? hb0 : hb1;
                float2 v = __ldcg((const float2*)&hsrc[threadIdx.x * 2]);
                hsh[threadIdx.x * 2 + 0] = v.x;
                hsh[threadIdx.x * 2 + 1] = v.y;
                __syncthreads();
            }
        }
        // group boundary: wait for next group's tile, then prefetch its first xg
        if (grp + 1 < NGRP) {
            wait_group(dir, grp + 1);
            const int tn = (grp + 1) * 128;
            const int sn = dir ? (SEQ - 1 - tn) : tn;
            xv = *(const float4*)&xg[sn * G4 + j * 4];
        }
    }
}

// =====================================================================
// fused persistent kernel:
//   phase A: ALL 152 CTAs produce the first PREF_TILES xg tiles (runway)
//   then:    128 rec CTAs run the recurrence; 24 workers produce the rest
// =====================================================================
__global__ void __launch_bounds__(256, 2) fused_main(
    const float* __restrict__ emb,
    const float* __restrict__ wih_f, const float* __restrict__ bih_f, const float* __restrict__ bhh_f,
    const float* __restrict__ wih_b, const float* __restrict__ bih_b, const float* __restrict__ bhh_b,
    const float* __restrict__ whh_f, const float* __restrict__ whh_b,
    const float* __restrict__ c0)
{
    __shared__ float sh[SH_FLOATS];              // union: rec uses 512, gemm uses all

    // phase A: cooperative runway production (2 tiles per CTA)
    for (int tile = blockIdx.x; tile < PREF_TILES; tile += GRID_CTAS)
        gemm_tile(sh, tile, emb, wih_f, bih_f, bhh_f, wih_b, bih_b, bhh_b);

    if (blockIdx.x < REC_CTAS) {
        rec_body(sh, whh_f, whh_b, c0);
    } else {
        const int worker = blockIdx.x - REC_CTAS;
        for (int tile = PREF_TILES + worker; tile < TOTAL_TILES; tile += GEMM_CTAS)
            gemm_tile(sh, tile, emb, wih_f, bih_f, bhh_f, wih_b, bih_b, bhh_b);
    }
}

// =====================================================================
// feats[t, j] = [hs_f | hs_b] . w_tag[j] + b_tag[j]
// =====================================================================
__global__ void feats_kernel(const float* __restrict__ w_tag,
                             const float* __restrict__ b_tag)
{
    const int t = blockIdx.x;
    const int w = threadIdx.x >> 5;              // 0..13 (tag)
    const int l = threadIdx.x & 31;
    const float* __restrict__ hf = &g_hs[0][t * HD];
    const float* __restrict__ hb = &g_hs[1][t * HD];
    const float* __restrict__ wt = &w_tag[w * 1024];

    float acc = 0.f;
    #pragma unroll
    for (int k = l; k < HD; k += 32)
        acc = fmaf(hf[k], wt[k], fmaf(hb[k], wt[HD + k], acc));
    #pragma unroll
    for (int off = 16; off > 0; off >>= 1)
        acc += __shfl_down_sync(0xffffffffu, acc, off);
    if (l == 0) g_feats[t * NTAG + w] = acc + b_tag[w];
}

// =====================================================================
// CRF chunk matrices (log-semiring): Ms <- M_t (o) Ms, 64 steps/chunk
// =====================================================================
__global__ void crf_chunk(const float* __restrict__ trans)
{
    __shared__ float Ms[NTAG][NTAG + 2];
    const int tid = threadIdx.x;                 // 0..195
    const int j = tid / NTAG;
    const int i = tid % NTAG;

    float trow[NTAG];
    #pragma unroll
    for (int k = 0; k < NTAG; k++) trow[k] = trans[j * NTAG + k];

    Ms[j][i] = (i == j) ? 0.f : NEGBIG;          // semiring identity
    __syncthreads();

    const int base = blockIdx.x * CHUNK;
    for (int t = base; t < base + CHUNK; t++) {
        float fj = g_feats[t * NTAG + j];
        float vals[NTAG];
        float m = NEGBIG;
        #pragma unroll
        for (int k = 0; k < NTAG; k++) {
            vals[k] = trow[k] + Ms[k][i];
            m = fmaxf(m, vals[k]);
        }
        float s = 0.f;
        #pragma unroll
        for (int k = 0; k < NTAG; k++) s += __expf(vals[k] - m);
        float nv = m + __logf(s) + fj;
        __syncthreads();
        Ms[j][i] = nv;
        __syncthreads();
    }
    g_chunkM[blockIdx.x][j][i] = Ms[j][i];
}

// =====================================================================
// gold score (parallel reduce) + chunk composition + final output
// =====================================================================
__global__ void crf_final(const float* __restrict__ trans,
                          const int* __restrict__ tags,
                          float* __restrict__ out)
{
    __shared__ float red[256];
    const int tid = threadIdx.x;

    float part = 0.f;
    for (int t = tid; t < SEQ; t += 256) {
        int tag  = tags[t];
        int prev = (t == 0) ? START_IDX : tags[t - 1];
        part += g_feats[t * NTAG + tag] + trans[tag * NTAG + prev];
    }
    red[tid] = part;
    __syncthreads();
    #pragma unroll
    for (int s = 128; s > 0; s >>= 1) {
        if (tid < s) red[tid] += red[tid + s];
        __syncthreads();
    }
    const float gold = red[0] + trans[STOP_IDX * NTAG + tags[SEQ - 1]];

    if (tid < 32) {
        const int l = tid;
        float fv = (l < NTAG) ? ((l == START_IDX) ? 0.f : NEGBIG) : NEGBIG;
        for (int cix = 0; cix < NCHUNK; cix++) {
            float vals[NTAG];
            float m = NEGBIG;
            #pragma unroll
            for (int i = 0; i < NTAG; i++) {
                float fvi = __shfl_sync(0xffffffffu, fv, i);
                float v = (l < NTAG) ? (g_chunkM[cix][l][i] + fvi) : NEGBIG;
                vals[i] = v;
                m = fmaxf(m, v);
            }
            float s = 0.f;
            #pragma unroll
            for (int i = 0; i < NTAG; i++) s += __expf(vals[i] - m);
            float nv = m + __logf(s);
            fv = (l < NTAG) ? nv : NEGBIG;
        }
        float v = (l < NTAG) ? (fv + trans[STOP_IDX * NTAG + l]) : NEGBIG;
        float m = v;
        #pragma unroll
        for (int off = 16; off > 0; off >>= 1)
            m = fmaxf(m, __shfl_xor_sync(0xffffffffu, m, off));
        float e = __expf(v - m);
        #pragma unroll
        for (int off = 16; off > 0; off >>= 1)
            e += __shfl_xor_sync(0xffffffffu, e, off);
        float fwd = m + __logf(e);
        if (l == 0) out[0] = fwd - gold;
    }
}

// =====================================================================
// launch
// =====================================================================
extern "C" void kernel_launch(void* const* d_in, const int* in_sizes, int n_in,
                              void* d_out, int out_size)
{
    const float* embeds = (const float*)d_in[0];
    const int*   tags   = (const int*)  d_in[1];
    const float* w_ih_f = (const float*)d_in[2];
    const float* w_hh_f = (const float*)d_in[3];
    const float* b_ih_f = (const float*)d_in[4];
    const float* b_hh_f = (const float*)d_in[5];
    const float* w_ih_b = (const float*)d_in[6];
    const float* w_hh_b = (const float*)d_in[7];
    const float* b_ih_b = (const float*)d_in[8];
    const float* b_hh_b = (const float*)d_in[9];
    const float* w_tag  = (const float*)d_in[10];
    const float* b_tag  = (const float*)d_in[11];
    const float* trans  = (const float*)d_in[12];
    const float* h0     = (const float*)d_in[13];
    const float* c0     = (const float*)d_in[14];
    float* out = (float*)d_out;

    init_state<<<1, 512>>>(h0);

    // 152 CTAs = GB300 SM count -> wave-1 places one CTA per SM
    fused_main<<<GRID_CTAS, 256>>>(embeds,
                                   w_ih_f, b_ih_f, b_hh_f,
                                   w_ih_b, b_ih_b, b_hh_b,
                                   w_hh_f, w_hh_b, c0);

    feats_kernel<<<SEQ, NTAG * 32>>>(w_tag, b_tag);

    crf_chunk<<<NCHUNK, NTAG * NTAG>>>(trans);

    crf_final<<<1, 256>>>(trans, tags, out);
}